// round 1
// baseline (speedup 1.0000x reference)
#include <cuda_runtime.h>
#include <cstdint>

#define NN 100000
#define FEAT 256

// Scratch (device globals — no allocation allowed)
__device__ float g_deg[NN];
__device__ float g_inv[NN];
__device__ float g_agg[(size_t)NN * FEAT];
__device__ float g_h1[(size_t)NN * FEAT];
__device__ float g_h2[(size_t)NN * FEAT];

__global__ void k_zero(float* __restrict__ p, int n4) {
    int i = blockIdx.x * blockDim.x + threadIdx.x;
    if (i < n4) reinterpret_cast<float4*>(p)[i] = make_float4(0.f, 0.f, 0.f, 0.f);
}

__global__ void k_deg(const int* __restrict__ dst, int E) {
    int e = blockIdx.x * blockDim.x + threadIdx.x;
    if (e < E) atomicAdd(&g_deg[dst[e]], 1.0f);
}

__global__ void k_inv(int n) {
    int i = blockIdx.x * blockDim.x + threadIdx.x;
    if (i < n) g_inv[i] = 1.0f / fmaxf(g_deg[i], 1.0f);
}

// One (edge, 4-float chunk) per thread: 64 threads per edge.
__global__ void k_agg(const float* __restrict__ h, const int* __restrict__ src,
                      const int* __restrict__ dst, int E) {
    long long tid = (long long)blockIdx.x * blockDim.x + threadIdx.x;
    int e = (int)(tid >> 6);
    if (e >= E) return;
    int c = ((int)tid & 63) << 2;
    int s = src[e];
    int d = dst[e];
    float4 v = *reinterpret_cast<const float4*>(h + (size_t)s * FEAT + c);
    float* addr = g_agg + (size_t)d * FEAT + c;
    asm volatile("red.global.add.v4.f32 [%0], {%1, %2, %3, %4};"
                 :: "l"(addr), "f"(v.x), "f"(v.y), "f"(v.z), "f"(v.w)
                 : "memory");
}

// Fused dual GEMM: C = A1 @ W1 + diag(g_inv) * A2 @ W2 + b, optional ReLU.
// Tiles: BM=64, BN=64, BK=16. 256 threads, 4x4 micro-tile per thread.
// A tiles stored k-major in smem -> all compute reads are LDS.128.
__global__ __launch_bounds__(256) void k_gemm(
    const float* __restrict__ A1, const float* __restrict__ A2,
    const float* __restrict__ W1, const float* __restrict__ W2,
    const float* __restrict__ bias, float* __restrict__ C,
    int M, int K, int NC, int relu)
{
    __shared__ float As1[16][68];
    __shared__ float As2[16][68];
    __shared__ float Bs1[16][68];
    __shared__ float Bs2[16][68];

    const int t  = threadIdx.x;
    const int tx = t & 15;
    const int ty = t >> 4;
    const int row0 = blockIdx.y * 64;
    const int col0 = blockIdx.x * 64;

    // Loader mapping
    const int li = t >> 2;            // 0..63 : A row within tile
    const int lk = (t & 3) * 4;       // 0,4,8,12 : k sub-offset (float4)
    const int wk = t >> 4;            // 0..15 : B k-row
    const int wc = (t & 15) * 4;      // 0..60 : B col offset (float4)

    const int  arow = row0 + li;
    const bool aval = arow < M;
    const float idg = aval ? g_inv[arow] : 0.0f;
    const float* a1p = A1 + (size_t)arow * K + lk;
    const float* a2p = A2 + (size_t)arow * K + lk;
    const float* w1p = W1 + (size_t)wk * NC + col0 + wc;
    const float* w2p = W2 + (size_t)wk * NC + col0 + wc;

    float acc[4][4];
#pragma unroll
    for (int r = 0; r < 4; r++)
#pragma unroll
        for (int c = 0; c < 4; c++) acc[r][c] = 0.0f;

    for (int k0 = 0; k0 < K; k0 += 16) {
        float4 a1 = make_float4(0.f, 0.f, 0.f, 0.f);
        float4 a2 = make_float4(0.f, 0.f, 0.f, 0.f);
        if (aval) {
            a1 = *reinterpret_cast<const float4*>(a1p + k0);
            a2 = *reinterpret_cast<const float4*>(a2p + k0);
        }
        a2.x *= idg; a2.y *= idg; a2.z *= idg; a2.w *= idg;
        As1[lk + 0][li] = a1.x; As1[lk + 1][li] = a1.y;
        As1[lk + 2][li] = a1.z; As1[lk + 3][li] = a1.w;
        As2[lk + 0][li] = a2.x; As2[lk + 1][li] = a2.y;
        As2[lk + 2][li] = a2.z; As2[lk + 3][li] = a2.w;
        *reinterpret_cast<float4*>(&Bs1[wk][wc]) =
            *reinterpret_cast<const float4*>(w1p + (size_t)k0 * NC);
        *reinterpret_cast<float4*>(&Bs2[wk][wc]) =
            *reinterpret_cast<const float4*>(w2p + (size_t)k0 * NC);
        __syncthreads();

#pragma unroll
        for (int k = 0; k < 16; k++) {
            float4 a1f = *reinterpret_cast<float4*>(&As1[k][ty * 4]);
            float4 a2f = *reinterpret_cast<float4*>(&As2[k][ty * 4]);
            float4 b1f = *reinterpret_cast<float4*>(&Bs1[k][tx * 4]);
            float4 b2f = *reinterpret_cast<float4*>(&Bs2[k][tx * 4]);
            const float a1v[4] = {a1f.x, a1f.y, a1f.z, a1f.w};
            const float a2v[4] = {a2f.x, a2f.y, a2f.z, a2f.w};
            const float b1v[4] = {b1f.x, b1f.y, b1f.z, b1f.w};
            const float b2v[4] = {b2f.x, b2f.y, b2f.z, b2f.w};
#pragma unroll
            for (int r = 0; r < 4; r++)
#pragma unroll
                for (int c = 0; c < 4; c++)
                    acc[r][c] += a1v[r] * b1v[c] + a2v[r] * b2v[c];
        }
        __syncthreads();
    }

    const float4 bv = *reinterpret_cast<const float4*>(bias + col0 + tx * 4);
    const float bvv[4] = {bv.x, bv.y, bv.z, bv.w};
#pragma unroll
    for (int r = 0; r < 4; r++) {
        int row = row0 + ty * 4 + r;
        if (row < M) {
            float4 o;
            float ov[4];
#pragma unroll
            for (int c = 0; c < 4; c++) {
                float v = acc[r][c] + bvv[c];
                if (relu) v = fmaxf(v, 0.0f);
                ov[c] = v;
            }
            o.x = ov[0]; o.y = ov[1]; o.z = ov[2]; o.w = ov[3];
            *reinterpret_cast<float4*>(C + (size_t)row * NC + col0 + tx * 4) = o;
        }
    }
}

extern "C" void kernel_launch(void* const* d_in, const int* in_sizes, int n_in,
                              void* d_out, int out_size) {
    const float* x   = (const float*)d_in[0];
    const int*   src = (const int*)d_in[1];
    const int*   dst = (const int*)d_in[2];
    const float* Ws1 = (const float*)d_in[3];
    const float* Wn1 = (const float*)d_in[4];
    const float* b1  = (const float*)d_in[5];
    const float* Ws2 = (const float*)d_in[6];
    const float* Wn2 = (const float*)d_in[7];
    const float* b2  = (const float*)d_in[8];
    const float* Ws3 = (const float*)d_in[9];
    const float* Wn3 = (const float*)d_in[10];
    const float* b3  = (const float*)d_in[11];
    float* out = (float*)d_out;

    const int N = in_sizes[0] / FEAT;   // 100000
    const int E = in_sizes[1];          // 800000
    const int NCLS = out_size / N;      // 64

    float *agg, *h1, *h2, *deg;
    cudaGetSymbolAddress((void**)&agg, g_agg);
    cudaGetSymbolAddress((void**)&h1,  g_h1);
    cudaGetSymbolAddress((void**)&h2,  g_h2);
    cudaGetSymbolAddress((void**)&deg, g_deg);

    const int ZT = 256;
    const long long aggThreads = (long long)E * 64;
    const int aggBlocks = (int)((aggThreads + 255) / 256);
    const int featVec4 = N * (FEAT / 4);

    // Degree + inverse degree
    k_zero<<<(N / 4 + ZT - 1) / ZT, ZT>>>(deg, N / 4);
    k_deg<<<(E + ZT - 1) / ZT, ZT>>>(dst, E);
    k_inv<<<(N + ZT - 1) / ZT, ZT>>>(N);

    dim3 g256(FEAT / 64, (N + 63) / 64);
    dim3 g64(NCLS / 64, (N + 63) / 64);

    // Layer 1
    k_zero<<<(featVec4 + ZT - 1) / ZT, ZT>>>(agg, featVec4);
    k_agg<<<aggBlocks, ZT>>>(x, src, dst, E);
    k_gemm<<<g256, 256>>>(x, agg, Ws1, Wn1, b1, h1, N, FEAT, FEAT, 1);

    // Layer 2
    k_zero<<<(featVec4 + ZT - 1) / ZT, ZT>>>(agg, featVec4);
    k_agg<<<aggBlocks, ZT>>>(h1, src, dst, E);
    k_gemm<<<g256, 256>>>(h1, agg, Ws2, Wn2, b2, h2, N, FEAT, FEAT, 1);

    // Layer 3 (no ReLU, 64 output classes)
    k_zero<<<(featVec4 + ZT - 1) / ZT, ZT>>>(agg, featVec4);
    k_agg<<<aggBlocks, ZT>>>(h2, src, dst, E);
    k_gemm<<<g64, 256>>>(h2, agg, Ws3, Wn3, b3, out, N, FEAT, NCLS, 0);
}

// round 3
// speedup vs baseline: 1.3739x; 1.3739x over previous
#include <cuda_runtime.h>
#include <cuda_bf16.h>
#include <cstdint>

#define NN   100000
#define MPAD 100096            // 782 * 128
#define FEAT 256
#define NTILES 782

// ---------------- device scratch (no allocation allowed) ----------------
__device__ float g_deg[NN];
__device__ float g_inv[NN];
__device__ float g_agg[(size_t)NN * FEAT];
__device__ float g_h1[(size_t)NN * FEAT];
__device__ float g_h2[(size_t)NN * FEAT];
__device__ __align__(16) __nv_bfloat16 g_a1h[(size_t)MPAD * FEAT];
__device__ __align__(16) __nv_bfloat16 g_a1l[(size_t)MPAD * FEAT];
__device__ __align__(16) __nv_bfloat16 g_a2h[(size_t)MPAD * FEAT];
__device__ __align__(16) __nv_bfloat16 g_a2l[(size_t)MPAD * FEAT];
__device__ __align__(16) __nv_bfloat16 g_wh[6][FEAT * FEAT];
__device__ __align__(16) __nv_bfloat16 g_wl[6][FEAT * FEAT];

// ---------------- helpers ----------------
__device__ __forceinline__ uint32_t smem_u32(const void* p) {
    uint32_t a;
    asm("{ .reg .u64 t; cvta.to.shared.u64 t, %1; cvt.u32.u64 %0, t; }" : "=r"(a) : "l"(p));
    return a;
}
__device__ __forceinline__ void cpa16(uint32_t dst, const void* src) {
    asm volatile("cp.async.cg.shared.global [%0], [%1], 16;" :: "r"(dst), "l"(src));
}

// ---------------- small kernels ----------------
__global__ void k_zero(float* __restrict__ p, int n4) {
    int i = blockIdx.x * blockDim.x + threadIdx.x;
    if (i < n4) reinterpret_cast<float4*>(p)[i] = make_float4(0.f, 0.f, 0.f, 0.f);
}
__global__ void k_deg(const int* __restrict__ dst, int E) {
    int e = blockIdx.x * blockDim.x + threadIdx.x;
    if (e < E) atomicAdd(&g_deg[dst[e]], 1.0f);
}
__global__ void k_inv(int n) {
    int i = blockIdx.x * blockDim.x + threadIdx.x;
    if (i < n) g_inv[i] = 1.0f / fmaxf(g_deg[i], 1.0f);
}
// edge scatter: 64 threads per edge, red.global.add.v4
__global__ void k_agg(const float* __restrict__ h, const int* __restrict__ src,
                      const int* __restrict__ dst, int E) {
    long long tid = (long long)blockIdx.x * blockDim.x + threadIdx.x;
    int e = (int)(tid >> 6);
    if (e >= E) return;
    int c = ((int)tid & 63) << 2;
    int s = src[e], d = dst[e];
    float4 v = *reinterpret_cast<const float4*>(h + (size_t)s * FEAT + c);
    float* addr = g_agg + (size_t)d * FEAT + c;
    asm volatile("red.global.add.v4.f32 [%0], {%1, %2, %3, %4};"
                 :: "l"(addr), "f"(v.x), "f"(v.y), "f"(v.z), "f"(v.w) : "memory");
}
// transpose + hi/lo split of weights: out[n][k] = W[k][n]; zero-pad n in [N, Npad)
__global__ void k_split_w(const float* __restrict__ W, int N, int Npad,
                          __nv_bfloat16* __restrict__ hi, __nv_bfloat16* __restrict__ lo) {
    int idx = blockIdx.x * blockDim.x + threadIdx.x;
    if (idx >= Npad * FEAT) return;
    int n = idx >> 8, k = idx & 255;
    float v = (n < N) ? W[(size_t)k * N + n] : 0.0f;
    __nv_bfloat16 h = __float2bfloat16(v);
    hi[(size_t)n * FEAT + k] = h;
    lo[(size_t)n * FEAT + k] = __float2bfloat16(v - __bfloat162float(h));
}
// split activations: A1 = h, A2 = agg * inv_deg; pad rows >= M with zeros
__global__ void k_prep_a(const float* __restrict__ h, int M) {
    size_t i = (size_t)blockIdx.x * blockDim.x + threadIdx.x;
    if (i >= (size_t)MPAD * FEAT) return;
    int row = (int)(i >> 8);
    float v1 = 0.f, v2 = 0.f;
    if (row < M) {
        v1 = h[i];
        v2 = g_agg[i] * g_inv[row];
    }
    __nv_bfloat16 h1 = __float2bfloat16(v1);
    __nv_bfloat16 h2 = __float2bfloat16(v2);
    g_a1h[i] = h1;
    g_a1l[i] = __float2bfloat16(v1 - __bfloat162float(h1));
    g_a2h[i] = h2;
    g_a2l[i] = __float2bfloat16(v2 - __bfloat162float(h2));
}

// ---------------- HMMA fused dual GEMM ----------------
// C[M,NC] = A1 @ W1^T + A2 @ W2^T + bias (3-term bf16 split per product).
// CTA tile 128x128, BK=32, 8 warps (2x4), warp tile 64x32.
// B operands stored [n][k] (k-contiguous) -> col-major for mma, plain ldmatrix.
#define SPAD 40   // smem row stride in bf16 (80B): conflict-free ldmatrix

__global__ __launch_bounds__(256) void k_mma(
    const __nv_bfloat16* __restrict__ b1h, const __nv_bfloat16* __restrict__ b1l,
    const __nv_bfloat16* __restrict__ b2h, const __nv_bfloat16* __restrict__ b2l,
    const float* __restrict__ bias, float* __restrict__ C,
    int M, int NC, int relu)
{
    __shared__ __nv_bfloat16 As[2][128][SPAD];
    __shared__ __nv_bfloat16 Bs[2][128][SPAD];

    const int t    = threadIdx.x;
    const int wid  = t >> 5;
    const int lane = t & 31;
    const int wm0  = (wid >> 2) << 6;      // 0 or 64
    const int wn0  = (wid & 3) << 5;       // 0,32,64,96
    const int row0 = blockIdx.y * 128;
    const int col0 = blockIdx.x * 128;

    const __nv_bfloat16* Aarr[4] = {g_a1h, g_a1l, g_a2h, g_a2l};
    const __nv_bfloat16* Barr[4] = {b1h, b1l, b2h, b2l};
    const int termA[6] = {0, 0, 1, 2, 2, 3};
    const int termB[6] = {0, 1, 0, 2, 3, 2};

    // loader mapping: 512 16B-chunks per tile, 2 per thread
    const int lrow0 = t >> 2;              // chunk rows: idx/4
    const int lc0   = (t & 3) << 3;        // bf16 col offset: (idx%4)*8

    float acc[4][4][4];
#pragma unroll
    for (int mi = 0; mi < 4; mi++)
#pragma unroll
        for (int ni = 0; ni < 4; ni++)
#pragma unroll
            for (int r = 0; r < 4; r++) acc[mi][ni][r] = 0.0f;

    const int NIT = 48;  // 6 terms x 8 k-chunks
    auto load_tile = [&](int it, int s) {
        const int term = it / 8, kc = it & 7;
        const __nv_bfloat16* ap = Aarr[termA[term]] + (size_t)row0 * FEAT + kc * 32;
        const __nv_bfloat16* bp = Barr[termB[term]] + (size_t)col0 * FEAT + kc * 32;
#pragma unroll
        for (int j = 0; j < 2; j++) {
            int row = lrow0 + j * 64;
            cpa16(smem_u32(&As[s][row][lc0]), ap + (size_t)row * FEAT + lc0);
            cpa16(smem_u32(&Bs[s][row][lc0]), bp + (size_t)row * FEAT + lc0);
        }
        asm volatile("cp.async.commit_group;" ::: "memory");
    };

    load_tile(0, 0);

    for (int it = 0; it < NIT; it++) {
        const int s = it & 1;
        if (it + 1 < NIT) {
            load_tile(it + 1, s ^ 1);
            asm volatile("cp.async.wait_group 1;" ::: "memory");
        } else {
            asm volatile("cp.async.wait_group 0;" ::: "memory");
        }
        __syncthreads();

#pragma unroll
        for (int ks = 0; ks < 2; ks++) {
            const int k0 = ks << 4;
            // A frags: 4 x ldmatrix.x4 (16m x 16k each)
            uint32_t a[4][4];
#pragma unroll
            for (int mi = 0; mi < 4; mi++) {
                uint32_t addr = smem_u32(
                    &As[s][wm0 + mi * 16 + (lane & 15)][k0 + ((lane >> 4) << 3)]);
                asm volatile("ldmatrix.sync.aligned.m8n8.x4.shared.b16 {%0,%1,%2,%3}, [%4];"
                             : "=r"(a[mi][0]), "=r"(a[mi][1]), "=r"(a[mi][2]), "=r"(a[mi][3])
                             : "r"(addr));
            }
            // B frags: 2 x ldmatrix.x4 (16n x 16k each) -> 4 n8-frags
            uint32_t b[8];
#pragma unroll
            for (int nb = 0; nb < 2; nb++) {
                uint32_t addr = smem_u32(
                    &Bs[s][wn0 + nb * 16 + (lane & 7) + ((lane >> 4) << 3)]
                       [k0 + (((lane >> 3) & 1) << 3)]);
                asm volatile("ldmatrix.sync.aligned.m8n8.x4.shared.b16 {%0,%1,%2,%3}, [%4];"
                             : "=r"(b[nb * 4 + 0]), "=r"(b[nb * 4 + 1]),
                               "=r"(b[nb * 4 + 2]), "=r"(b[nb * 4 + 3])
                             : "r"(addr));
            }
#pragma unroll
            for (int mi = 0; mi < 4; mi++)
#pragma unroll
                for (int ni = 0; ni < 4; ni++) {
                    asm volatile(
                        "mma.sync.aligned.m16n8k16.row.col.f32.bf16.bf16.f32 "
                        "{%0,%1,%2,%3}, {%4,%5,%6,%7}, {%8,%9}, {%0,%1,%2,%3};"
                        : "+f"(acc[mi][ni][0]), "+f"(acc[mi][ni][1]),
                          "+f"(acc[mi][ni][2]), "+f"(acc[mi][ni][3])
                        : "r"(a[mi][0]), "r"(a[mi][1]), "r"(a[mi][2]), "r"(a[mi][3]),
                          "r"(b[ni * 2]), "r"(b[ni * 2 + 1]));
                }
        }
        __syncthreads();
    }

    // epilogue: c0,c1 -> (row, col..col+1); c2,c3 -> (row+8, col..col+1)
    const int crow = (lane >> 2);
    const int ccol = (lane & 3) << 1;
#pragma unroll
    for (int mi = 0; mi < 4; mi++) {
#pragma unroll
        for (int ni = 0; ni < 4; ni++) {
            int col = col0 + wn0 + ni * 8 + ccol;
            if (col >= NC) continue;
            float bx = bias[col], by = bias[col + 1];
#pragma unroll
            for (int h = 0; h < 2; h++) {
                int row = row0 + wm0 + mi * 16 + crow + h * 8;
                if (row < M) {
                    float vx = acc[mi][ni][h * 2 + 0] + bx;
                    float vy = acc[mi][ni][h * 2 + 1] + by;
                    if (relu) { vx = fmaxf(vx, 0.f); vy = fmaxf(vy, 0.f); }
                    float2 o = make_float2(vx, vy);
                    *reinterpret_cast<float2*>(C + (size_t)row * NC + col) = o;
                }
            }
        }
    }
}

// ---------------- launch ----------------
extern "C" void kernel_launch(void* const* d_in, const int* in_sizes, int n_in,
                              void* d_out, int out_size) {
    const float* x   = (const float*)d_in[0];
    const int*   src = (const int*)d_in[1];
    const int*   dst = (const int*)d_in[2];
    const float* Ws1 = (const float*)d_in[3];
    const float* Wn1 = (const float*)d_in[4];
    const float* b1  = (const float*)d_in[5];
    const float* Ws2 = (const float*)d_in[6];
    const float* Wn2 = (const float*)d_in[7];
    const float* b2  = (const float*)d_in[8];
    const float* Ws3 = (const float*)d_in[9];
    const float* Wn3 = (const float*)d_in[10];
    const float* b3  = (const float*)d_in[11];
    float* out = (float*)d_out;

    const int N = in_sizes[0] / FEAT;   // 100000
    const int E = in_sizes[1];          // 800000
    const int NCLS = out_size / N;      // 64

    float *agg, *h1, *h2, *deg;
    cudaGetSymbolAddress((void**)&agg, g_agg);
    cudaGetSymbolAddress((void**)&h1,  g_h1);
    cudaGetSymbolAddress((void**)&h2,  g_h2);
    cudaGetSymbolAddress((void**)&deg, g_deg);
    __nv_bfloat16 *wh, *wl;
    cudaGetSymbolAddress((void**)&wh, g_wh);
    cudaGetSymbolAddress((void**)&wl, g_wl);
    auto WH = [&](int i) { return wh + (size_t)i * FEAT * FEAT; };
    auto WL = [&](int i) { return wl + (size_t)i * FEAT * FEAT; };

    const int ZT = 256;
    const long long aggThreads = (long long)E * 64;
    const int aggBlocks = (int)((aggThreads + 255) / 256);
    const int featVec4 = N * (FEAT / 4);
    const int prepBlocks = (int)(((size_t)MPAD * FEAT + 255) / 256);

    // weights: transpose + hi/lo split ([n][k] layout)
    k_split_w<<<(256 * FEAT + ZT - 1) / ZT, ZT>>>(Ws1, 256, 256, WH(0), WL(0));
    k_split_w<<<(256 * FEAT + ZT - 1) / ZT, ZT>>>(Wn1, 256, 256, WH(1), WL(1));
    k_split_w<<<(256 * FEAT + ZT - 1) / ZT, ZT>>>(Ws2, 256, 256, WH(2), WL(2));
    k_split_w<<<(256 * FEAT + ZT - 1) / ZT, ZT>>>(Wn2, 256, 256, WH(3), WL(3));
    k_split_w<<<(128 * FEAT + ZT - 1) / ZT, ZT>>>(Ws3, 64, 128, WH(4), WL(4));
    k_split_w<<<(128 * FEAT + ZT - 1) / ZT, ZT>>>(Wn3, 64, 128, WH(5), WL(5));

    // degrees
    k_zero<<<(N / 4 + ZT - 1) / ZT, ZT>>>(deg, N / 4);
    k_deg<<<(E + ZT - 1) / ZT, ZT>>>(dst, E);
    k_inv<<<(N + ZT - 1) / ZT, ZT>>>(N);

    dim3 gridL12(2, NTILES);
    dim3 gridL3(1, NTILES);

    // layer 1
    k_zero<<<(featVec4 + ZT - 1) / ZT, ZT>>>(agg, featVec4);
    k_agg<<<aggBlocks, ZT>>>(x, src, dst, E);
    k_prep_a<<<prepBlocks, ZT>>>(x, N);
    k_mma<<<gridL12, 256>>>(WH(0), WL(0), WH(1), WL(1), b1, h1, N, 256, 1);

    // layer 2
    k_zero<<<(featVec4 + ZT - 1) / ZT, ZT>>>(agg, featVec4);
    k_agg<<<aggBlocks, ZT>>>(h1, src, dst, E);
    k_prep_a<<<prepBlocks, ZT>>>(h1, N);
    k_mma<<<gridL12, 256>>>(WH(2), WL(2), WH(3), WL(3), b2, h2, N, 256, 1);

    // layer 3 (no ReLU, 64 classes)
    k_zero<<<(featVec4 + ZT - 1) / ZT, ZT>>>(agg, featVec4);
    k_agg<<<aggBlocks, ZT>>>(h2, src, dst, E);
    k_prep_a<<<prepBlocks, ZT>>>(h2, N);
    k_mma<<<gridL3, 256>>>(WH(4), WL(4), WH(5), WL(5), b3, out, N, NCLS, 0);
}

// round 4
// speedup vs baseline: 1.9005x; 1.3833x over previous
#include <cuda_runtime.h>
#include <cuda_bf16.h>
#include <cstdint>

#define NN   100000
#define MPAD 100096            // 782 * 128
#define FEAT 256
#define NT   782
#define SPAD 40

// ---------------- device scratch ----------------
__device__ float g_deg[NN];
__device__ float g_inv[NN];
__device__ float g_agg[(size_t)NN * 256];
__device__ float g_yz[(size_t)MPAD * 512];
__device__ __align__(16) __nv_bfloat16 g_hh[(size_t)MPAD * FEAT];
__device__ __align__(16) __nv_bfloat16 g_hl[(size_t)MPAD * FEAT];
__device__ __align__(16) __nv_bfloat16 g_wh[2][512 * 256];
__device__ __align__(16) __nv_bfloat16 g_wl[2][512 * 256];
__device__ __align__(16) __nv_bfloat16 g_w3h[128 * 256];
__device__ __align__(16) __nv_bfloat16 g_w3l[128 * 256];

// ---------------- helpers ----------------
__device__ __forceinline__ uint32_t smem_u32(const void* p) {
    uint32_t a;
    asm("{ .reg .u64 t; cvta.to.shared.u64 t, %1; cvt.u32.u64 %0, t; }" : "=r"(a) : "l"(p));
    return a;
}
__device__ __forceinline__ void cpa16(uint32_t dst, const void* src) {
    asm volatile("cp.async.cg.shared.global [%0], [%1], 16;" :: "r"(dst), "l"(src));
}

// ---------------- small kernels ----------------
__global__ void k_zero(float* __restrict__ p, int n4) {
    int i = blockIdx.x * blockDim.x + threadIdx.x;
    if (i < n4) reinterpret_cast<float4*>(p)[i] = make_float4(0.f, 0.f, 0.f, 0.f);
}
__global__ void k_deg(const int* __restrict__ dst, int E) {
    int e = blockIdx.x * blockDim.x + threadIdx.x;
    if (e < E) atomicAdd(&g_deg[dst[e]], 1.0f);
}
__global__ void k_inv(int n) {
    int i = blockIdx.x * blockDim.x + threadIdx.x;
    if (i < n) g_inv[i] = 1.0f / fmaxf(g_deg[i], 1.0f);
}
// edge scatter on transformed feats: agg[dst][0..W) += yz[src][CB..CB+W)
template<int W>
__global__ void k_agg(const float* __restrict__ yz, const int* __restrict__ src,
                      const int* __restrict__ dst, int E, int stride, int cb) {
    const int TPE = W / 4;
    long long tid = (long long)blockIdx.x * blockDim.x + threadIdx.x;
    int e = (int)(tid / TPE);
    if (e >= E) return;
    int c = ((int)(tid % TPE)) << 2;
    int s = src[e], d = dst[e];
    float4 v = *reinterpret_cast<const float4*>(yz + (size_t)s * stride + cb + c);
    float* addr = g_agg + (size_t)d * W + c;
    asm volatile("red.global.add.v4.f32 [%0], {%1, %2, %3, %4};"
                 :: "l"(addr), "f"(v.x), "f"(v.y), "f"(v.z), "f"(v.w) : "memory");
}
// transpose + split W[k][n] -> cat[nb+n][k] hi/lo
__global__ void k_split_w(const float* __restrict__ W, int Nw, int nb,
                          __nv_bfloat16* __restrict__ hi, __nv_bfloat16* __restrict__ lo) {
    int idx = blockIdx.x * blockDim.x + threadIdx.x;
    if (idx >= Nw * FEAT) return;
    int n = idx >> 8, k = idx & 255;
    float v = W[(size_t)k * Nw + n];
    __nv_bfloat16 h = __float2bfloat16(v);
    hi[(size_t)(nb + n) * FEAT + k] = h;
    lo[(size_t)(nb + n) * FEAT + k] = __float2bfloat16(v - __bfloat162float(h));
}
__device__ __forceinline__ uint32_t pack2(float a, float b) {
    __nv_bfloat162 p(__float2bfloat16(a), __float2bfloat16(b));
    return *reinterpret_cast<uint32_t*>(&p);
}
__device__ __forceinline__ void split_store4(size_t idx, float v0, float v1, float v2, float v3) {
    __nv_bfloat16 h0 = __float2bfloat16(v0), h1 = __float2bfloat16(v1);
    __nv_bfloat16 h2 = __float2bfloat16(v2), h3 = __float2bfloat16(v3);
    uint2 hpack, lpack;
    {
        __nv_bfloat162 a(h0, h1), b(h2, h3);
        hpack.x = *reinterpret_cast<uint32_t*>(&a);
        hpack.y = *reinterpret_cast<uint32_t*>(&b);
    }
    lpack.x = pack2(v0 - __bfloat162float(h0), v1 - __bfloat162float(h1));
    lpack.y = pack2(v2 - __bfloat162float(h2), v3 - __bfloat162float(h3));
    *reinterpret_cast<uint2*>(g_hh + idx) = hpack;
    *reinterpret_cast<uint2*>(g_hl + idx) = lpack;
}
// split x -> hh/hl with zero pad
__global__ void k_split_x(const float* __restrict__ x, int M) {
    size_t i4 = (size_t)blockIdx.x * blockDim.x + threadIdx.x;
    if (i4 >= (size_t)MPAD * 64) return;
    int row = (int)(i4 >> 6);
    float4 v = make_float4(0.f, 0.f, 0.f, 0.f);
    if (row < M) v = reinterpret_cast<const float4*>(x)[i4];
    split_store4(i4 * 4, v.x, v.y, v.z, v.w);
}
// combine layers 1/2: h_next = relu(ys + inv*aggz + b) -> bf16 split (pad rows -> 0)
__global__ void k_combine(const float* __restrict__ bias, int M) {
    size_t i4 = (size_t)blockIdx.x * blockDim.x + threadIdx.x;
    if (i4 >= (size_t)MPAD * 64) return;
    int row = (int)(i4 >> 6);
    int c = ((int)(i4 & 63)) << 2;
    float v0 = 0.f, v1 = 0.f, v2 = 0.f, v3 = 0.f;
    if (row < M) {
        float inv = g_inv[row];
        float4 ys = *reinterpret_cast<const float4*>(g_yz + (size_t)row * 512 + c);
        float4 az = *reinterpret_cast<const float4*>(g_agg + (size_t)row * 256 + c);
        float4 bv = *reinterpret_cast<const float4*>(bias + c);
        v0 = fmaxf(ys.x + inv * az.x + bv.x, 0.f);
        v1 = fmaxf(ys.y + inv * az.y + bv.y, 0.f);
        v2 = fmaxf(ys.z + inv * az.z + bv.z, 0.f);
        v3 = fmaxf(ys.w + inv * az.w + bv.w, 0.f);
    }
    split_store4(i4 * 4, v0, v1, v2, v3);
}
// combine layer 3: out = ys + inv*aggz + b (no relu), 64 classes
__global__ void k_combine3(const float* __restrict__ bias, float* __restrict__ out, int M) {
    size_t i4 = (size_t)blockIdx.x * blockDim.x + threadIdx.x;
    if (i4 >= (size_t)M * 16) return;
    int row = (int)(i4 >> 4);
    int c = ((int)(i4 & 15)) << 2;
    float inv = g_inv[row];
    float4 ys = *reinterpret_cast<const float4*>(g_yz + (size_t)row * 128 + c);
    float4 az = *reinterpret_cast<const float4*>(g_agg + (size_t)row * 64 + c);
    float4 bv = *reinterpret_cast<const float4*>(bias + c);
    float4 o;
    o.x = ys.x + inv * az.x + bv.x;
    o.y = ys.y + inv * az.y + bv.y;
    o.z = ys.z + inv * az.z + bv.z;
    o.w = ys.w + inv * az.w + bv.w;
    *reinterpret_cast<float4*>(out + (size_t)row * 64 + c) = o;
}

// ---------------- HMMA GEMM: C[MPAD, NOUT] = A @ Bcat^T (3-chain bf16 split) ----------------
// CTA tile 128 x BN, 8 warps (2m x 4n), warp tile 64 x (BN/4).
// Per K-chunk (32): load Ah,Al,Bh,Bl tiles; run 3 chains on resident tiles.
template<int BN, int NF>   // NF = BN/32 n8-frags per warp
__global__ __launch_bounds__(256) void k_mma(
    const __nv_bfloat16* __restrict__ Ah, const __nv_bfloat16* __restrict__ Al,
    const __nv_bfloat16* __restrict__ Bh, const __nv_bfloat16* __restrict__ Bl,
    float* __restrict__ C, int NOUT)
{
    extern __shared__ __nv_bfloat16 dyn[];
    constexpr int AS  = 128 * SPAD;
    constexpr int BS  = BN * SPAD;
    constexpr int STG = 2 * AS + 2 * BS;

    const int t    = threadIdx.x;
    const int wid  = t >> 5;
    const int lane = t & 31;
    const int wm0  = (wid >> 2) << 6;
    const int wn0  = (wid & 3) * (BN / 4);
    const int row0 = blockIdx.y * 128;
    const int col0 = blockIdx.x * BN;

    const int lr = t >> 2;            // 0..63
    const int lc = (t & 3) << 3;      // 0,8,16,24

    float acc[4][NF][4];
#pragma unroll
    for (int mi = 0; mi < 4; mi++)
#pragma unroll
        for (int ni = 0; ni < NF; ni++)
#pragma unroll
            for (int r = 0; r < 4; r++) acc[mi][ni][r] = 0.0f;

    auto load_chunk = [&](int kc, int s) {
        __nv_bfloat16* dA0 = dyn + s * STG;
        __nv_bfloat16* dA1 = dA0 + AS;
        __nv_bfloat16* dB0 = dA0 + 2 * AS;
        __nv_bfloat16* dB1 = dB0 + BS;
        const __nv_bfloat16* aph = Ah + (size_t)row0 * FEAT + kc * 32;
        const __nv_bfloat16* apl = Al + (size_t)row0 * FEAT + kc * 32;
        const __nv_bfloat16* bph = Bh + (size_t)col0 * FEAT + kc * 32;
        const __nv_bfloat16* bpl = Bl + (size_t)col0 * FEAT + kc * 32;
#pragma unroll
        for (int j = 0; j < 2; j++) {
            int row = lr + j * 64;
            cpa16(smem_u32(dA0 + row * SPAD + lc), aph + (size_t)row * FEAT + lc);
            cpa16(smem_u32(dA1 + row * SPAD + lc), apl + (size_t)row * FEAT + lc);
        }
#pragma unroll
        for (int j = 0; j < BN / 64; j++) {
            int row = lr + j * 64;
            cpa16(smem_u32(dB0 + row * SPAD + lc), bph + (size_t)row * FEAT + lc);
            cpa16(smem_u32(dB1 + row * SPAD + lc), bpl + (size_t)row * FEAT + lc);
        }
        asm volatile("cp.async.commit_group;" ::: "memory");
    };

    load_chunk(0, 0);
    load_chunk(1, 1);

    for (int kc = 0; kc < 8; kc++) {
        const int s = kc % 3;
        if (kc + 2 < 8) {
            load_chunk(kc + 2, (kc + 2) % 3);
            asm volatile("cp.async.wait_group 2;" ::: "memory");
        } else if (kc + 1 < 8) {
            asm volatile("cp.async.wait_group 1;" ::: "memory");
        } else {
            asm volatile("cp.async.wait_group 0;" ::: "memory");
        }
        __syncthreads();

        __nv_bfloat16* dA0 = dyn + s * STG;
        __nv_bfloat16* dA1 = dA0 + AS;
        __nv_bfloat16* dB0 = dA0 + 2 * AS;
        __nv_bfloat16* dB1 = dB0 + BS;

#pragma unroll
        for (int ks = 0; ks < 2; ks++) {
            const int k0 = ks << 4;
            const int arow = wm0 + (lane & 15);
            const int acol = k0 + ((lane >> 4) << 3);
            const int brow = wn0 + (lane & 7) + ((lane >> 4) << 3);
            const int bcol = k0 + (((lane >> 3) & 1) << 3);

            uint32_t aH[4][4], aL[4][4], bH[NF * 2], bL[NF * 2];
#pragma unroll
            for (int mi = 0; mi < 4; mi++) {
                uint32_t ad = smem_u32(dA0 + (arow + mi * 16) * SPAD + acol);
                asm volatile("ldmatrix.sync.aligned.m8n8.x4.shared.b16 {%0,%1,%2,%3}, [%4];"
                             : "=r"(aH[mi][0]), "=r"(aH[mi][1]), "=r"(aH[mi][2]), "=r"(aH[mi][3])
                             : "r"(ad));
            }
#pragma unroll
            for (int nb = 0; nb < NF / 2; nb++) {
                uint32_t ad = smem_u32(dB0 + (brow + nb * 16) * SPAD + bcol);
                asm volatile("ldmatrix.sync.aligned.m8n8.x4.shared.b16 {%0,%1,%2,%3}, [%4];"
                             : "=r"(bH[nb * 4 + 0]), "=r"(bH[nb * 4 + 1]),
                               "=r"(bH[nb * 4 + 2]), "=r"(bH[nb * 4 + 3])
                             : "r"(ad));
            }
#pragma unroll
            for (int mi = 0; mi < 4; mi++)
#pragma unroll
                for (int ni = 0; ni < NF; ni++)
                    asm volatile(
                        "mma.sync.aligned.m16n8k16.row.col.f32.bf16.bf16.f32 "
                        "{%0,%1,%2,%3}, {%4,%5,%6,%7}, {%8,%9}, {%0,%1,%2,%3};"
                        : "+f"(acc[mi][ni][0]), "+f"(acc[mi][ni][1]),
                          "+f"(acc[mi][ni][2]), "+f"(acc[mi][ni][3])
                        : "r"(aH[mi][0]), "r"(aH[mi][1]), "r"(aH[mi][2]), "r"(aH[mi][3]),
                          "r"(bH[ni * 2]), "r"(bH[ni * 2 + 1]));
#pragma unroll
            for (int mi = 0; mi < 4; mi++) {
                uint32_t ad = smem_u32(dA1 + (arow + mi * 16) * SPAD + acol);
                asm volatile("ldmatrix.sync.aligned.m8n8.x4.shared.b16 {%0,%1,%2,%3}, [%4];"
                             : "=r"(aL[mi][0]), "=r"(aL[mi][1]), "=r"(aL[mi][2]), "=r"(aL[mi][3])
                             : "r"(ad));
            }
#pragma unroll
            for (int mi = 0; mi < 4; mi++)
#pragma unroll
                for (int ni = 0; ni < NF; ni++)
                    asm volatile(
                        "mma.sync.aligned.m16n8k16.row.col.f32.bf16.bf16.f32 "
                        "{%0,%1,%2,%3}, {%4,%5,%6,%7}, {%8,%9}, {%0,%1,%2,%3};"
                        : "+f"(acc[mi][ni][0]), "+f"(acc[mi][ni][1]),
                          "+f"(acc[mi][ni][2]), "+f"(acc[mi][ni][3])
                        : "r"(aL[mi][0]), "r"(aL[mi][1]), "r"(aL[mi][2]), "r"(aL[mi][3]),
                          "r"(bH[ni * 2]), "r"(bH[ni * 2 + 1]));
#pragma unroll
            for (int nb = 0; nb < NF / 2; nb++) {
                uint32_t ad = smem_u32(dB1 + (brow + nb * 16) * SPAD + bcol);
                asm volatile("ldmatrix.sync.aligned.m8n8.x4.shared.b16 {%0,%1,%2,%3}, [%4];"
                             : "=r"(bL[nb * 4 + 0]), "=r"(bL[nb * 4 + 1]),
                               "=r"(bL[nb * 4 + 2]), "=r"(bL[nb * 4 + 3])
                             : "r"(ad));
            }
#pragma unroll
            for (int mi = 0; mi < 4; mi++)
#pragma unroll
                for (int ni = 0; ni < NF; ni++)
                    asm volatile(
                        "mma.sync.aligned.m16n8k16.row.col.f32.bf16.bf16.f32 "
                        "{%0,%1,%2,%3}, {%4,%5,%6,%7}, {%8,%9}, {%0,%1,%2,%3};"
                        : "+f"(acc[mi][ni][0]), "+f"(acc[mi][ni][1]),
                          "+f"(acc[mi][ni][2]), "+f"(acc[mi][ni][3])
                        : "r"(aH[mi][0]), "r"(aH[mi][1]), "r"(aH[mi][2]), "r"(aH[mi][3]),
                          "r"(bL[ni * 2]), "r"(bL[ni * 2 + 1]));
        }
        __syncthreads();
    }

    // epilogue: raw accumulators -> C (bias/relu handled downstream)
    const int crow = lane >> 2;
    const int ccol = (lane & 3) << 1;
#pragma unroll
    for (int mi = 0; mi < 4; mi++)
#pragma unroll
        for (int ni = 0; ni < NF; ni++) {
            int col = col0 + wn0 + ni * 8 + ccol;
#pragma unroll
            for (int h = 0; h < 2; h++) {
                int row = row0 + wm0 + mi * 16 + crow + h * 8;
                *reinterpret_cast<float2*>(C + (size_t)row * NOUT + col) =
                    make_float2(acc[mi][ni][h * 2 + 0], acc[mi][ni][h * 2 + 1]);
            }
        }
}

// ---------------- launch ----------------
extern "C" void kernel_launch(void* const* d_in, const int* in_sizes, int n_in,
                              void* d_out, int out_size) {
    const float* x   = (const float*)d_in[0];
    const int*   src = (const int*)d_in[1];
    const int*   dst = (const int*)d_in[2];
    const float* Ws1 = (const float*)d_in[3];
    const float* Wn1 = (const float*)d_in[4];
    const float* b1  = (const float*)d_in[5];
    const float* Ws2 = (const float*)d_in[6];
    const float* Wn2 = (const float*)d_in[7];
    const float* b2  = (const float*)d_in[8];
    const float* Ws3 = (const float*)d_in[9];
    const float* Wn3 = (const float*)d_in[10];
    const float* b3  = (const float*)d_in[11];
    float* out = (float*)d_out;

    const int N = in_sizes[0] / FEAT;   // 100000
    const int E = in_sizes[1];          // 800000

    float *agg, *yz, *deg;
    cudaGetSymbolAddress((void**)&agg, g_agg);
    cudaGetSymbolAddress((void**)&yz,  g_yz);
    cudaGetSymbolAddress((void**)&deg, g_deg);
    __nv_bfloat16 *hh, *hl, *wh, *wl, *w3h, *w3l;
    cudaGetSymbolAddress((void**)&hh, g_hh);
    cudaGetSymbolAddress((void**)&hl, g_hl);
    cudaGetSymbolAddress((void**)&wh, g_wh);
    cudaGetSymbolAddress((void**)&wl, g_wl);
    cudaGetSymbolAddress((void**)&w3h, g_w3h);
    cudaGetSymbolAddress((void**)&w3l, g_w3l);
    auto WH = [&](int i) { return wh + (size_t)i * 512 * 256; };
    auto WL = [&](int i) { return wl + (size_t)i * 512 * 256; };

    constexpr int SM256 = (2 * 128 * SPAD + 2 * 256 * SPAD) * 3 * 2;  // 184320 B
    constexpr int SM128 = (2 * 128 * SPAD + 2 * 128 * SPAD) * 3 * 2;  // 122880 B
    cudaFuncSetAttribute(k_mma<256, 8>, cudaFuncAttributeMaxDynamicSharedMemorySize, SM256);
    cudaFuncSetAttribute(k_mma<128, 4>, cudaFuncAttributeMaxDynamicSharedMemorySize, SM128);

    const int ZT = 256;
    const int splitBlocks = (int)(((size_t)MPAD * 64 + ZT - 1) / ZT);
    const long long agg256T = (long long)E * 64;
    const int agg256B = (int)((agg256T + 255) / 256);
    const long long agg64T = (long long)E * 16;
    const int agg64B = (int)((agg64T + 255) / 256);

    // weights: cat + transpose + split
    k_split_w<<<(256 * FEAT + ZT - 1) / ZT, ZT>>>(Ws1, 256, 0,   WH(0), WL(0));
    k_split_w<<<(256 * FEAT + ZT - 1) / ZT, ZT>>>(Wn1, 256, 256, WH(0), WL(0));
    k_split_w<<<(256 * FEAT + ZT - 1) / ZT, ZT>>>(Ws2, 256, 0,   WH(1), WL(1));
    k_split_w<<<(256 * FEAT + ZT - 1) / ZT, ZT>>>(Wn2, 256, 256, WH(1), WL(1));
    k_split_w<<<(64 * FEAT + ZT - 1) / ZT, ZT>>>(Ws3, 64, 0,   w3h, w3l);
    k_split_w<<<(64 * FEAT + ZT - 1) / ZT, ZT>>>(Wn3, 64, 64,  w3h, w3l);

    // degrees
    k_zero<<<(N / 4 + ZT - 1) / ZT, ZT>>>(deg, N / 4);
    k_deg<<<(E + ZT - 1) / ZT, ZT>>>(dst, E);
    k_inv<<<(N + ZT - 1) / ZT, ZT>>>(N);

    // x -> bf16 splits
    k_split_x<<<splitBlocks, ZT>>>(x, N);

    dim3 g12(2, NT);
    dim3 g3(1, NT);

    // layer 1
    k_mma<256, 8><<<g12, 256, SM256>>>(hh, hl, WH(0), WL(0), yz, 512);
    k_zero<<<(N * 64 + ZT - 1) / ZT, ZT>>>(agg, N * 64);
    k_agg<256><<<agg256B, ZT>>>(yz, src, dst, E, 512, 256);
    k_combine<<<splitBlocks, ZT>>>(b1, N);

    // layer 2
    k_mma<256, 8><<<g12, 256, SM256>>>(hh, hl, WH(1), WL(1), yz, 512);
    k_zero<<<(N * 64 + ZT - 1) / ZT, ZT>>>(agg, N * 64);
    k_agg<256><<<agg256B, ZT>>>(yz, src, dst, E, 512, 256);
    k_combine<<<splitBlocks, ZT>>>(b2, N);

    // layer 3
    k_mma<128, 4><<<g3, 256, SM128>>>(hh, hl, w3h, w3l, yz, 128);
    k_zero<<<(N * 16 + ZT - 1) / ZT, ZT>>>(agg, N * 16);
    k_agg<64><<<agg64B, ZT>>>(yz, src, dst, E, 128, 64);
    k_combine3<<<(N * 16 + ZT - 1) / ZT, ZT>>>(b3, out, N);
}

// round 5
// speedup vs baseline: 1.9631x; 1.0329x over previous
#include <cuda_runtime.h>
#include <cuda_fp16.h>
#include <cstdint>

#define NN   100000
#define MPAD 100096            // 782 * 128
#define FEAT 256
#define NT   782
#define SPAD 72                // smem row stride in half (144B), conflict-free ldmatrix

// ---------------- device scratch ----------------
__device__ float g_deg[NN];               // zero-init; k_inv restores zeros
__device__ float g_inv[NN];
__device__ float g_agg[(size_t)NN * 256]; // zero-init; combine kernels restore zeros
__device__ __align__(16) __half g_yz[(size_t)MPAD * 512];
__device__ __align__(16) __half g_h[(size_t)MPAD * FEAT];
__device__ __align__(16) __half g_w[2][512 * 256];
__device__ __align__(16) __half g_w3[128 * 256];

// ---------------- helpers ----------------
__device__ __forceinline__ uint32_t smem_u32(const void* p) {
    uint32_t a;
    asm("{ .reg .u64 t; cvta.to.shared.u64 t, %1; cvt.u32.u64 %0, t; }" : "=r"(a) : "l"(p));
    return a;
}
__device__ __forceinline__ void cpa16(uint32_t dst, const void* src) {
    asm volatile("cp.async.cg.shared.global [%0], [%1], 16;" :: "r"(dst), "l"(src));
}

// ---------------- small kernels ----------------
__global__ void k_deg(const int* __restrict__ dst, int E) {
    int e = blockIdx.x * blockDim.x + threadIdx.x;
    if (e < E) atomicAdd(&g_deg[dst[e]], 1.0f);
}
__global__ void k_inv(int n) {
    int i = blockIdx.x * blockDim.x + threadIdx.x;
    if (i < n) {
        g_inv[i] = 1.0f / fmaxf(g_deg[i], 1.0f);
        g_deg[i] = 0.0f;                       // restore for next replay
    }
}
// weights: cat + transpose + fp16:  w[n][k] = (n<Nw ? Ws : Wn)[k][n%Nw]
__global__ void k_cvt_w(const float* __restrict__ Ws, const float* __restrict__ Wn,
                        int Nw, __half* __restrict__ w) {
    int idx = blockIdx.x * blockDim.x + threadIdx.x;
    if (idx >= 2 * Nw * FEAT) return;
    int n = idx >> 8, k = idx & 255;
    float v = (n < Nw) ? Ws[(size_t)k * Nw + n] : Wn[(size_t)k * Nw + (n - Nw)];
    w[idx] = __float2half_rn(v);
}
// x fp32 -> g_h fp16, zero-pad rows >= M
__global__ void k_cvt_x(const float* __restrict__ x, int M) {
    size_t tid = (size_t)blockIdx.x * blockDim.x + threadIdx.x;
    if (tid >= (size_t)MPAD * 64) return;
    int row = (int)(tid >> 6);
    float4 v = make_float4(0.f, 0.f, 0.f, 0.f);
    if (row < M) v = reinterpret_cast<const float4*>(x)[tid];
    uint2 o;
    __half2 p0 = __float22half2_rn(make_float2(v.x, v.y));
    __half2 p1 = __float22half2_rn(make_float2(v.z, v.w));
    o.x = *reinterpret_cast<uint32_t*>(&p0);
    o.y = *reinterpret_cast<uint32_t*>(&p1);
    *reinterpret_cast<uint2*>(g_h + tid * 4) = o;
}
// edge scatter: agg[dst][c..c+8) += z[src][c..c+8)  (z = fp16 cols CB.. of yz)
template<int W>
__global__ void k_agg(const __half* __restrict__ yz, const int* __restrict__ src,
                      const int* __restrict__ dst, int E, int stride, int cb) {
    const int TPE = W / 8;
    long long tid = (long long)blockIdx.x * blockDim.x + threadIdx.x;
    int e = (int)(tid / TPE);
    if (e >= E) return;
    int c = ((int)(tid % TPE)) << 3;
    int s = src[e], d = dst[e];
    uint4 raw = *reinterpret_cast<const uint4*>(yz + (size_t)s * stride + cb + c);
    const __half2* hp = reinterpret_cast<const __half2*>(&raw);
    float2 f0 = __half22float2(hp[0]);
    float2 f1 = __half22float2(hp[1]);
    float2 f2 = __half22float2(hp[2]);
    float2 f3 = __half22float2(hp[3]);
    float* addr = g_agg + (size_t)d * W + c;
    asm volatile("red.global.add.v4.f32 [%0], {%1, %2, %3, %4};"
                 :: "l"(addr), "f"(f0.x), "f"(f0.y), "f"(f1.x), "f"(f1.y) : "memory");
    asm volatile("red.global.add.v4.f32 [%0], {%1, %2, %3, %4};"
                 :: "l"(addr + 4), "f"(f2.x), "f"(f2.y), "f"(f3.x), "f"(f3.y) : "memory");
}
// combine L1/2: h = relu(ys + inv*agg + b) -> fp16; zero pad rows; re-zero agg
__global__ void k_combine(const float* __restrict__ bias, int M) {
    size_t tid = (size_t)blockIdx.x * blockDim.x + threadIdx.x;
    if (tid >= (size_t)MPAD * 64) return;
    int row = (int)(tid >> 6);
    int c = ((int)(tid & 63)) << 2;
    float v0 = 0.f, v1 = 0.f, v2 = 0.f, v3 = 0.f;
    if (row < M) {
        float inv = g_inv[row];
        uint2 raw = *reinterpret_cast<const uint2*>(g_yz + (size_t)row * 512 + c);
        const __half2* hp = reinterpret_cast<const __half2*>(&raw);
        float2 y0 = __half22float2(hp[0]);
        float2 y1 = __half22float2(hp[1]);
        float4 az = *reinterpret_cast<const float4*>(g_agg + (size_t)row * 256 + c);
        *reinterpret_cast<float4*>(g_agg + (size_t)row * 256 + c) =
            make_float4(0.f, 0.f, 0.f, 0.f);
        float4 bv = *reinterpret_cast<const float4*>(bias + c);
        v0 = fmaxf(y0.x + inv * az.x + bv.x, 0.f);
        v1 = fmaxf(y0.y + inv * az.y + bv.y, 0.f);
        v2 = fmaxf(y1.x + inv * az.z + bv.z, 0.f);
        v3 = fmaxf(y1.y + inv * az.w + bv.w, 0.f);
    }
    uint2 o;
    __half2 p0 = __float22half2_rn(make_float2(v0, v1));
    __half2 p1 = __float22half2_rn(make_float2(v2, v3));
    o.x = *reinterpret_cast<uint32_t*>(&p0);
    o.y = *reinterpret_cast<uint32_t*>(&p1);
    *reinterpret_cast<uint2*>(g_h + tid * 4) = o;
}
// combine L3: out = ys + inv*agg + b (fp32, 64 classes); re-zero agg
__global__ void k_combine3(const float* __restrict__ bias, float* __restrict__ out, int M) {
    size_t tid = (size_t)blockIdx.x * blockDim.x + threadIdx.x;
    if (tid >= (size_t)M * 16) return;
    int row = (int)(tid >> 4);
    int c = ((int)(tid & 15)) << 2;
    float inv = g_inv[row];
    uint2 raw = *reinterpret_cast<const uint2*>(g_yz + (size_t)row * 128 + c);
    const __half2* hp = reinterpret_cast<const __half2*>(&raw);
    float2 y0 = __half22float2(hp[0]);
    float2 y1 = __half22float2(hp[1]);
    float4 az = *reinterpret_cast<const float4*>(g_agg + (size_t)row * 64 + c);
    *reinterpret_cast<float4*>(g_agg + (size_t)row * 64 + c) =
        make_float4(0.f, 0.f, 0.f, 0.f);
    float4 bv = *reinterpret_cast<const float4*>(bias + c);
    float4 o;
    o.x = y0.x + inv * az.x + bv.x;
    o.y = y0.y + inv * az.y + bv.y;
    o.z = y1.x + inv * az.z + bv.z;
    o.w = y1.y + inv * az.w + bv.w;
    *reinterpret_cast<float4*>(out + (size_t)row * 64 + c) = o;
}

// ---------------- fp16 HMMA GEMM: Y[MPAD, NOUT](fp16) = A @ B^T ----------------
// CTA tile 128 x BN, 8 warps (2m x 4n), warp tile 64 x BN/4. BK=64, 3-stage cp.async.
template<int BN, int NF>
__global__ __launch_bounds__(256) void k_mma(
    const __half* __restrict__ A, const __half* __restrict__ B,
    __half* __restrict__ Y, int NOUT)
{
    extern __shared__ __half dyn[];
    constexpr int AS  = 128 * SPAD;
    constexpr int BS  = BN * SPAD;
    constexpr int STG = AS + BS;

    const int t    = threadIdx.x;
    const int wid  = t >> 5;
    const int lane = t & 31;
    const int wm0  = (wid >> 2) << 6;
    const int wn0  = (wid & 3) * (BN / 4);
    const int row0 = blockIdx.y * 128;
    const int col0 = blockIdx.x * BN;

    const int lr = t >> 3;            // chunk row base 0..31
    const int lc = (t & 7) << 3;      // half-col offset 0..56

    float acc[4][NF][4];
#pragma unroll
    for (int mi = 0; mi < 4; mi++)
#pragma unroll
        for (int ni = 0; ni < NF; ni++)
#pragma unroll
            for (int r = 0; r < 4; r++) acc[mi][ni][r] = 0.0f;

    auto load_chunk = [&](int kc, int s) {
        __half* dA = dyn + s * STG;
        __half* dB = dA + AS;
        const __half* ap = A + (size_t)row0 * FEAT + kc * 64;
        const __half* bp = B + (size_t)col0 * FEAT + kc * 64;
#pragma unroll
        for (int j = 0; j < 4; j++) {
            int row = lr + j * 32;
            cpa16(smem_u32(dA + row * SPAD + lc), ap + (size_t)row * FEAT + lc);
        }
#pragma unroll
        for (int j = 0; j < BN / 32; j++) {
            int row = lr + j * 32;
            cpa16(smem_u32(dB + row * SPAD + lc), bp + (size_t)row * FEAT + lc);
        }
        asm volatile("cp.async.commit_group;" ::: "memory");
    };

    load_chunk(0, 0);
    load_chunk(1, 1);

    for (int kc = 0; kc < 4; kc++) {
        const int s = kc % 3;
        if (kc + 2 < 4) {
            load_chunk(kc + 2, (kc + 2) % 3);
            asm volatile("cp.async.wait_group 2;" ::: "memory");
        } else if (kc + 1 < 4) {
            asm volatile("cp.async.wait_group 1;" ::: "memory");
        } else {
            asm volatile("cp.async.wait_group 0;" ::: "memory");
        }
        __syncthreads();

        __half* dA = dyn + s * STG;
        __half* dB = dA + AS;

#pragma unroll
        for (int ks = 0; ks < 4; ks++) {
            const int k0 = ks << 4;
            const int arow = wm0 + (lane & 15);
            const int acol = k0 + ((lane >> 4) << 3);
            const int brow = wn0 + (lane & 7) + ((lane >> 4) << 3);
            const int bcol = k0 + (((lane >> 3) & 1) << 3);

            uint32_t a[4][4], b[NF * 2];
#pragma unroll
            for (int mi = 0; mi < 4; mi++) {
                uint32_t ad = smem_u32(dA + (arow + mi * 16) * SPAD + acol);
                asm volatile("ldmatrix.sync.aligned.m8n8.x4.shared.b16 {%0,%1,%2,%3}, [%4];"
                             : "=r"(a[mi][0]), "=r"(a[mi][1]), "=r"(a[mi][2]), "=r"(a[mi][3])
                             : "r"(ad));
            }
#pragma unroll
            for (int nb = 0; nb < NF / 2; nb++) {
                uint32_t ad = smem_u32(dB + (brow + nb * 16) * SPAD + bcol);
                asm volatile("ldmatrix.sync.aligned.m8n8.x4.shared.b16 {%0,%1,%2,%3}, [%4];"
                             : "=r"(b[nb * 4 + 0]), "=r"(b[nb * 4 + 1]),
                               "=r"(b[nb * 4 + 2]), "=r"(b[nb * 4 + 3])
                             : "r"(ad));
            }
#pragma unroll
            for (int mi = 0; mi < 4; mi++)
#pragma unroll
                for (int ni = 0; ni < NF; ni++)
                    asm volatile(
                        "mma.sync.aligned.m16n8k16.row.col.f32.f16.f16.f32 "
                        "{%0,%1,%2,%3}, {%4,%5,%6,%7}, {%8,%9}, {%0,%1,%2,%3};"
                        : "+f"(acc[mi][ni][0]), "+f"(acc[mi][ni][1]),
                          "+f"(acc[mi][ni][2]), "+f"(acc[mi][ni][3])
                        : "r"(a[mi][0]), "r"(a[mi][1]), "r"(a[mi][2]), "r"(a[mi][3]),
                          "r"(b[ni * 2]), "r"(b[ni * 2 + 1]));
        }
        __syncthreads();
    }

    // epilogue: fp32 acc -> fp16 Y
    const int crow = lane >> 2;
    const int ccol = (lane & 3) << 1;
#pragma unroll
    for (int mi = 0; mi < 4; mi++)
#pragma unroll
        for (int ni = 0; ni < NF; ni++) {
            int col = col0 + wn0 + ni * 8 + ccol;
#pragma unroll
            for (int h = 0; h < 2; h++) {
                int row = row0 + wm0 + mi * 16 + crow + h * 8;
                __half2 p = __float22half2_rn(
                    make_float2(acc[mi][ni][h * 2 + 0], acc[mi][ni][h * 2 + 1]));
                *reinterpret_cast<uint32_t*>(Y + (size_t)row * NOUT + col) =
                    *reinterpret_cast<uint32_t*>(&p);
            }
        }
}

// ---------------- launch ----------------
extern "C" void kernel_launch(void* const* d_in, const int* in_sizes, int n_in,
                              void* d_out, int out_size) {
    const float* x   = (const float*)d_in[0];
    const int*   src = (const int*)d_in[1];
    const int*   dst = (const int*)d_in[2];
    const float* Ws1 = (const float*)d_in[3];
    const float* Wn1 = (const float*)d_in[4];
    const float* b1  = (const float*)d_in[5];
    const float* Ws2 = (const float*)d_in[6];
    const float* Wn2 = (const float*)d_in[7];
    const float* b2  = (const float*)d_in[8];
    const float* Ws3 = (const float*)d_in[9];
    const float* Wn3 = (const float*)d_in[10];
    const float* b3  = (const float*)d_in[11];
    float* out = (float*)d_out;

    const int N = in_sizes[0] / FEAT;   // 100000
    const int E = in_sizes[1];          // 800000

    __half *yz, *h, *w0, *w1, *w3;
    cudaGetSymbolAddress((void**)&yz, g_yz);
    cudaGetSymbolAddress((void**)&h,  g_h);
    cudaGetSymbolAddress((void**)&w0, g_w);
    cudaGetSymbolAddress((void**)&w3, g_w3);
    w1 = w0 + (size_t)512 * 256;

    constexpr int SM256 = (128 * SPAD + 256 * SPAD) * 3 * 2;  // 165888 B
    constexpr int SM128 = (128 * SPAD + 128 * SPAD) * 3 * 2;  // 110592 B
    cudaFuncSetAttribute(k_mma<256, 8>, cudaFuncAttributeMaxDynamicSharedMemorySize, SM256);
    cudaFuncSetAttribute(k_mma<128, 4>, cudaFuncAttributeMaxDynamicSharedMemorySize, SM128);

    const int ZT = 256;
    const int cvtBlocks = (int)(((size_t)MPAD * 64 + ZT - 1) / ZT);
    const int agg256B = (int)(((long long)E * 32 + 255) / 256);
    const int agg64B  = (int)(((long long)E * 8 + 255) / 256);

    // weights -> fp16 concat
    k_cvt_w<<<(2 * 256 * FEAT + ZT - 1) / ZT, ZT>>>(Ws1, Wn1, 256, w0);
    k_cvt_w<<<(2 * 256 * FEAT + ZT - 1) / ZT, ZT>>>(Ws2, Wn2, 256, w1);
    k_cvt_w<<<(2 * 64 * FEAT + ZT - 1) / ZT, ZT>>>(Ws3, Wn3, 64, w3);

    // degrees (g_deg self-restores to zero in k_inv)
    k_deg<<<(E + ZT - 1) / ZT, ZT>>>(dst, E);
    k_inv<<<(N + ZT - 1) / ZT, ZT>>>(N);

    // x -> fp16
    k_cvt_x<<<cvtBlocks, ZT>>>(x, N);

    dim3 g12(2, NT);
    dim3 g3(1, NT);

    // layer 1
    k_mma<256, 8><<<g12, 256, SM256>>>(h, w0, yz, 512);
    k_agg<256><<<agg256B, ZT>>>(yz, src, dst, E, 512, 256);
    k_combine<<<cvtBlocks, ZT>>>(b1, N);

    // layer 2
    k_mma<256, 8><<<g12, 256, SM256>>>(h, w1, yz, 512);
    k_agg<256><<<agg256B, ZT>>>(yz, src, dst, E, 512, 256);
    k_combine<<<cvtBlocks, ZT>>>(b2, N);

    // layer 3
    k_mma<128, 4><<<g3, 256, SM128>>>(h, w3, yz, 128);
    k_agg<64><<<agg64B, ZT>>>(yz, src, dst, E, 128, 64);
    k_combine3<<<(N * 16 + ZT - 1) / ZT, ZT>>>(b3, out, N);
}

// round 7
// speedup vs baseline: 5.7481x; 2.9281x over previous
#include <cuda_runtime.h>
#include <cuda_fp16.h>
#include <cstdint>

#define NN   100000
#define MPAD 100096            // 782 * 128
#define FEAT 256
#define NT   782
#define SPAD 72
#define EMAX 800000
#define NB   391               // ceil(NN/256)

// ---------------- device scratch ----------------
__device__ int   g_degi[NN];           // zero-init; k_off restores zeros
__device__ float g_inv[NN];
__device__ int   g_off[NN + 1];
__device__ int   g_cursor[NN];
__device__ int   g_srcl[EMAX];
__device__ int   g_bsum[NB];
__device__ int   g_boff[NB];
__device__ __align__(16) __half g_yz[(size_t)MPAD * 512];
__device__ __align__(16) __half g_h[(size_t)MPAD * FEAT];
__device__ __align__(16) __half g_w[2][512 * 256];
__device__ __align__(16) __half g_w3[128 * 256];

// ---------------- helpers ----------------
__device__ __forceinline__ uint32_t smem_u32(const void* p) {
    uint32_t a;
    asm("{ .reg .u64 t; cvta.to.shared.u64 t, %1; cvt.u32.u64 %0, t; }" : "=r"(a) : "l"(p));
    return a;
}
__device__ __forceinline__ void cpa16(uint32_t dst, const void* src) {
    asm volatile("cp.async.cg.shared.global [%0], [%1], 16;" :: "r"(dst), "l"(src));
}

// ---------------- CSR build ----------------
__global__ void k_degi(const int* __restrict__ dst, int E) {
    int e = blockIdx.x * blockDim.x + threadIdx.x;
    if (e < E) atomicAdd(&g_degi[dst[e]], 1);
}
__global__ void k_bsum() {
    __shared__ int s[256];
    int i = blockIdx.x * 256 + threadIdx.x;
    s[threadIdx.x] = (i < NN) ? g_degi[i] : 0;
    __syncthreads();
    for (int st = 128; st > 0; st >>= 1) {
        if (threadIdx.x < st) s[threadIdx.x] += s[threadIdx.x + st];
        __syncthreads();
    }
    if (threadIdx.x == 0) g_bsum[blockIdx.x] = s[0];
}
__global__ void k_bscan() {
    __shared__ int s[512];
    int t = threadIdx.x;
    int v = (t < NB) ? g_bsum[t] : 0;
    s[t] = v;
    __syncthreads();
    for (int st = 1; st < 512; st <<= 1) {
        int add = (t >= st) ? s[t - st] : 0;
        __syncthreads();
        s[t] += add;
        __syncthreads();
    }
    if (t < NB) g_boff[t] = s[t] - v;     // exclusive
}
__global__ void k_off(int E) {
    __shared__ int s[256];
    int i = blockIdx.x * 256 + threadIdx.x;
    int deg = (i < NN) ? g_degi[i] : 0;
    s[threadIdx.x] = deg;
    __syncthreads();
    for (int st = 1; st < 256; st <<= 1) {
        int add = (threadIdx.x >= st) ? s[threadIdx.x - st] : 0;
        __syncthreads();
        s[threadIdx.x] += add;
        __syncthreads();
    }
    if (i < NN) {
        int off = g_boff[blockIdx.x] + s[threadIdx.x] - deg;
        g_off[i] = off;
        g_cursor[i] = off;
        g_inv[i] = 1.0f / fmaxf((float)deg, 1.0f);
        g_degi[i] = 0;                    // restore for next replay
        if (i == NN - 1) g_off[NN] = E;
    }
}
__global__ void k_fill(const int* __restrict__ src, const int* __restrict__ dst, int E) {
    int e = blockIdx.x * blockDim.x + threadIdx.x;
    if (e < E) {
        int pos = atomicAdd(&g_cursor[dst[e]], 1);
        g_srcl[pos] = src[e];
    }
}

// ---------------- convert kernels ----------------
__global__ void k_cvt_w(const float* __restrict__ Ws, const float* __restrict__ Wn,
                        int Nw, __half* __restrict__ w) {
    int idx = blockIdx.x * blockDim.x + threadIdx.x;
    if (idx >= 2 * Nw * FEAT) return;
    int n = idx >> 8, k = idx & 255;
    float v = (n < Nw) ? Ws[(size_t)k * Nw + n] : Wn[(size_t)k * Nw + (n - Nw)];
    w[idx] = __float2half_rn(v);
}
__global__ void k_cvt_x(const float* __restrict__ x, int M) {
    size_t tid = (size_t)blockIdx.x * blockDim.x + threadIdx.x;
    if (tid >= (size_t)MPAD * 64) return;
    int row = (int)(tid >> 6);
    float4 v = make_float4(0.f, 0.f, 0.f, 0.f);
    if (row < M) v = reinterpret_cast<const float4*>(x)[tid];
    uint2 o;
    __half2 p0 = __float22half2_rn(make_float2(v.x, v.y));
    __half2 p1 = __float22half2_rn(make_float2(v.z, v.w));
    o.x = *reinterpret_cast<uint32_t*>(&p0);
    o.y = *reinterpret_cast<uint32_t*>(&p1);
    *reinterpret_cast<uint2*>(g_h + tid * 4) = o;
}

// ---------------- fused gather + combine ----------------
__device__ __forceinline__ void acc8(float* acc, uint4 raw) {
    const __half2* hp = reinterpret_cast<const __half2*>(&raw);
#pragma unroll
    for (int q = 0; q < 4; q++) {
        float2 f = __half22float2(hp[q]);
        acc[q * 2 + 0] += f.x;
        acc[q * 2 + 1] += f.y;
    }
}
// layers 1/2: one warp per node, lane owns 8 cols of 256.
// h[node] = relu(ys + inv * sum_z + bias) -> fp16
__global__ void k_gather(const float* __restrict__ bias, int M) {
    int wid  = threadIdx.x >> 5;
    int lane = threadIdx.x & 31;
    int node = blockIdx.x * (blockDim.x >> 5) + wid;
    if (node >= M) return;
    int beg = g_off[node], end = g_off[node + 1];
    const __half* z = g_yz + 256 + lane * 8;   // z-half of yz rows
    float acc[8] = {0.f, 0.f, 0.f, 0.f, 0.f, 0.f, 0.f, 0.f};
    int j = beg;
    for (; j + 2 <= end; j += 2) {
        int s0 = g_srcl[j], s1 = g_srcl[j + 1];
        uint4 r0 = *reinterpret_cast<const uint4*>(z + (size_t)s0 * 512);
        uint4 r1 = *reinterpret_cast<const uint4*>(z + (size_t)s1 * 512);
        acc8(acc, r0);
        acc8(acc, r1);
    }
    if (j < end) {
        int s0 = g_srcl[j];
        uint4 r0 = *reinterpret_cast<const uint4*>(z + (size_t)s0 * 512);
        acc8(acc, r0);
    }
    float inv = g_inv[node];
    uint4 rs = *reinterpret_cast<const uint4*>(g_yz + (size_t)node * 512 + lane * 8);
    const __half2* sp = reinterpret_cast<const __half2*>(&rs);
    float4 bva = *reinterpret_cast<const float4*>(bias + lane * 8);
    float4 bvb = *reinterpret_cast<const float4*>(bias + lane * 8 + 4);
    float bv[8] = {bva.x, bva.y, bva.z, bva.w, bvb.x, bvb.y, bvb.z, bvb.w};
    float v[8];
#pragma unroll
    for (int q = 0; q < 4; q++) {
        float2 ys = __half22float2(sp[q]);
        v[q * 2 + 0] = fmaxf(ys.x + inv * acc[q * 2 + 0] + bv[q * 2 + 0], 0.f);
        v[q * 2 + 1] = fmaxf(ys.y + inv * acc[q * 2 + 1] + bv[q * 2 + 1], 0.f);
    }
    uint4 o;
    __half2 p0 = __float22half2_rn(make_float2(v[0], v[1]));
    __half2 p1 = __float22half2_rn(make_float2(v[2], v[3]));
    __half2 p2 = __float22half2_rn(make_float2(v[4], v[5]));
    __half2 p3 = __float22half2_rn(make_float2(v[6], v[7]));
    o.x = *reinterpret_cast<uint32_t*>(&p0);
    o.y = *reinterpret_cast<uint32_t*>(&p1);
    o.z = *reinterpret_cast<uint32_t*>(&p2);
    o.w = *reinterpret_cast<uint32_t*>(&p3);
    *reinterpret_cast<uint4*>(g_h + (size_t)node * 256 + lane * 8) = o;
}
// layer 3: 8 lanes per node (4 nodes/warp), lane owns 8 of 64 cols, fp32 out.
__global__ void k_gather3(const float* __restrict__ bias, float* __restrict__ out, int M) {
    int wid  = threadIdx.x >> 5;
    int lane = threadIdx.x & 31;
    int node = (blockIdx.x * (blockDim.x >> 5) + wid) * 4 + (lane >> 3);
    int sub  = lane & 7;
    if (node >= M) return;
    int beg = g_off[node], end = g_off[node + 1];
    const __half* z = g_yz + 64 + sub * 8;
    float acc[8] = {0.f, 0.f, 0.f, 0.f, 0.f, 0.f, 0.f, 0.f};
    int j = beg;
    for (; j + 2 <= end; j += 2) {
        int s0 = g_srcl[j], s1 = g_srcl[j + 1];
        uint4 r0 = *reinterpret_cast<const uint4*>(z + (size_t)s0 * 128);
        uint4 r1 = *reinterpret_cast<const uint4*>(z + (size_t)s1 * 128);
        acc8(acc, r0);
        acc8(acc, r1);
    }
    if (j < end) {
        int s0 = g_srcl[j];
        uint4 r0 = *reinterpret_cast<const uint4*>(z + (size_t)s0 * 128);
        acc8(acc, r0);
    }
    float inv = g_inv[node];
    uint4 rs = *reinterpret_cast<const uint4*>(g_yz + (size_t)node * 128 + sub * 8);
    const __half2* sp = reinterpret_cast<const __half2*>(&rs);
    float4 bva = *reinterpret_cast<const float4*>(bias + sub * 8);
    float4 bvb = *reinterpret_cast<const float4*>(bias + sub * 8 + 4);
    float bv[8] = {bva.x, bva.y, bva.z, bva.w, bvb.x, bvb.y, bvb.z, bvb.w};
    float v[8];
#pragma unroll
    for (int q = 0; q < 4; q++) {
        float2 ys = __half22float2(sp[q]);
        v[q * 2 + 0] = ys.x + inv * acc[q * 2 + 0] + bv[q * 2 + 0];
        v[q * 2 + 1] = ys.y + inv * acc[q * 2 + 1] + bv[q * 2 + 1];
    }
    float* op = out + (size_t)node * 64 + sub * 8;
    *reinterpret_cast<float4*>(op)     = make_float4(v[0], v[1], v[2], v[3]);
    *reinterpret_cast<float4*>(op + 4) = make_float4(v[4], v[5], v[6], v[7]);
}

// ---------------- fp16 HMMA GEMM ----------------
template<int BN, int NF>
__global__ __launch_bounds__(256) void k_mma(
    const __half* __restrict__ A, const __half* __restrict__ B,
    __half* __restrict__ Y, int NOUT)
{
    extern __shared__ __half dyn[];
    constexpr int AS  = 128 * SPAD;
    constexpr int BS  = BN * SPAD;
    constexpr int STG = AS + BS;

    const int t    = threadIdx.x;
    const int wid  = t >> 5;
    const int lane = t & 31;
    const int wm0  = (wid >> 2) << 6;
    const int wn0  = (wid & 3) * (BN / 4);
    const int row0 = blockIdx.y * 128;
    const int col0 = blockIdx.x * BN;

    const int lr = t >> 3;
    const int lc = (t & 7) << 3;

    float acc[4][NF][4];
#pragma unroll
    for (int mi = 0; mi < 4; mi++)
#pragma unroll
        for (int ni = 0; ni < NF; ni++)
#pragma unroll
            for (int r = 0; r < 4; r++) acc[mi][ni][r] = 0.0f;

    auto load_chunk = [&](int kc, int s) {
        __half* dA = dyn + s * STG;
        __half* dB = dA + AS;
        const __half* ap = A + (size_t)row0 * FEAT + kc * 64;
        const __half* bp = B + (size_t)col0 * FEAT + kc * 64;
#pragma unroll
        for (int j = 0; j < 4; j++) {
            int row = lr + j * 32;
            cpa16(smem_u32(dA + row * SPAD + lc), ap + (size_t)row * FEAT + lc);
        }
#pragma unroll
        for (int j = 0; j < BN / 32; j++) {
            int row = lr + j * 32;
            cpa16(smem_u32(dB + row * SPAD + lc), bp + (size_t)row * FEAT + lc);
        }
        asm volatile("cp.async.commit_group;" ::: "memory");
    };

    load_chunk(0, 0);
    load_chunk(1, 1);

    for (int kc = 0; kc < 4; kc++) {
        const int s = kc % 3;
        if (kc + 2 < 4) {
            load_chunk(kc + 2, (kc + 2) % 3);
            asm volatile("cp.async.wait_group 2;" ::: "memory");
        } else if (kc + 1 < 4) {
            asm volatile("cp.async.wait_group 1;" ::: "memory");
        } else {
            asm volatile("cp.async.wait_group 0;" ::: "memory");
        }
        __syncthreads();

        __half* dA = dyn + s * STG;
        __half* dB = dA + AS;

#pragma unroll
        for (int ks = 0; ks < 4; ks++) {
            const int k0 = ks << 4;
            const int arow = wm0 + (lane & 15);
            const int acol = k0 + ((lane >> 4) << 3);
            const int brow = wn0 + (lane & 7) + ((lane >> 4) << 3);
            const int bcol = k0 + (((lane >> 3) & 1) << 3);

            uint32_t a[4][4], b[NF * 2];
#pragma unroll
            for (int mi = 0; mi < 4; mi++) {
                uint32_t ad = smem_u32(dA + (arow + mi * 16) * SPAD + acol);
                asm volatile("ldmatrix.sync.aligned.m8n8.x4.shared.b16 {%0,%1,%2,%3}, [%4];"
                             : "=r"(a[mi][0]), "=r"(a[mi][1]), "=r"(a[mi][2]), "=r"(a[mi][3])
                             : "r"(ad));
            }
#pragma unroll
            for (int nb = 0; nb < NF / 2; nb++) {
                uint32_t ad = smem_u32(dB + (brow + nb * 16) * SPAD + bcol);
                asm volatile("ldmatrix.sync.aligned.m8n8.x4.shared.b16 {%0,%1,%2,%3}, [%4];"
                             : "=r"(b[nb * 4 + 0]), "=r"(b[nb * 4 + 1]),
                               "=r"(b[nb * 4 + 2]), "=r"(b[nb * 4 + 3])
                             : "r"(ad));
            }
#pragma unroll
            for (int mi = 0; mi < 4; mi++)
#pragma unroll
                for (int ni = 0; ni < NF; ni++)
                    asm volatile(
                        "mma.sync.aligned.m16n8k16.row.col.f32.f16.f16.f32 "
                        "{%0,%1,%2,%3}, {%4,%5,%6,%7}, {%8,%9}, {%0,%1,%2,%3};"
                        : "+f"(acc[mi][ni][0]), "+f"(acc[mi][ni][1]),
                          "+f"(acc[mi][ni][2]), "+f"(acc[mi][ni][3])
                        : "r"(a[mi][0]), "r"(a[mi][1]), "r"(a[mi][2]), "r"(a[mi][3]),
                          "r"(b[ni * 2]), "r"(b[ni * 2 + 1]));
        }
        __syncthreads();
    }

    const int crow = lane >> 2;
    const int ccol = (lane & 3) << 1;
#pragma unroll
    for (int mi = 0; mi < 4; mi++)
#pragma unroll
        for (int ni = 0; ni < NF; ni++) {
            int col = col0 + wn0 + ni * 8 + ccol;
#pragma unroll
            for (int h = 0; h < 2; h++) {
                int row = row0 + wm0 + mi * 16 + crow + h * 8;
                __half2 p = __float22half2_rn(
                    make_float2(acc[mi][ni][h * 2 + 0], acc[mi][ni][h * 2 + 1]));
                *reinterpret_cast<uint32_t*>(Y + (size_t)row * NOUT + col) =
                    *reinterpret_cast<uint32_t*>(&p);
            }
        }
}

// ---------------- launch ----------------
extern "C" void kernel_launch(void* const* d_in, const int* in_sizes, int n_in,
                              void* d_out, int out_size) {
    const float* x   = (const float*)d_in[0];
    const int*   src = (const int*)d_in[1];
    const int*   dst = (const int*)d_in[2];
    const float* Ws1 = (const float*)d_in[3];
    const float* Wn1 = (const float*)d_in[4];
    const float* b1  = (const float*)d_in[5];
    const float* Ws2 = (const float*)d_in[6];
    const float* Wn2 = (const float*)d_in[7];
    const float* b2  = (const float*)d_in[8];
    const float* Ws3 = (const float*)d_in[9];
    const float* Wn3 = (const float*)d_in[10];
    const float* b3  = (const float*)d_in[11];
    float* out = (float*)d_out;

    const int N = in_sizes[0] / FEAT;   // 100000
    const int E = in_sizes[1];          // 800000

    __half *yz, *h, *w0, *w1, *w3;
    cudaGetSymbolAddress((void**)&yz, g_yz);
    cudaGetSymbolAddress((void**)&h,  g_h);
    cudaGetSymbolAddress((void**)&w0, g_w);
    cudaGetSymbolAddress((void**)&w3, g_w3);
    w1 = w0 + (size_t)512 * 256;

    constexpr int SM256 = (128 * SPAD + 256 * SPAD) * 3 * 2;
    constexpr int SM128 = (128 * SPAD + 128 * SPAD) * 3 * 2;
    cudaFuncSetAttribute(k_mma<256, 8>, cudaFuncAttributeMaxDynamicSharedMemorySize, SM256);
    cudaFuncSetAttribute(k_mma<128, 4>, cudaFuncAttributeMaxDynamicSharedMemorySize, SM128);

    const int ZT = 256;
    const int cvtBlocks = (int)(((size_t)MPAD * 64 + ZT - 1) / ZT);

    // weights -> fp16 concat
    k_cvt_w<<<(2 * 256 * FEAT + ZT - 1) / ZT, ZT>>>(Ws1, Wn1, 256, w0);
    k_cvt_w<<<(2 * 256 * FEAT + ZT - 1) / ZT, ZT>>>(Ws2, Wn2, 256, w1);
    k_cvt_w<<<(2 * 64 * FEAT + ZT - 1) / ZT, ZT>>>(Ws3, Wn3, 64, w3);

    // CSR build (degi self-restores in k_off)
    k_degi<<<(E + ZT - 1) / ZT, ZT>>>(dst, E);
    k_bsum<<<NB, 256>>>();
    k_bscan<<<1, 512>>>();
    k_off<<<NB, 256>>>(E);
    k_fill<<<(E + ZT - 1) / ZT, ZT>>>(src, dst, E);

    // x -> fp16
    k_cvt_x<<<cvtBlocks, ZT>>>(x, N);

    dim3 g12(2, NT);
    dim3 g3(1, NT);
    const int gatherB = (N + 7) / 8;          // 8 warps/block, 1 node/warp
    const int gather3B = (N + 31) / 32;       // 8 warps/block, 4 nodes/warp

    // layer 1
    k_mma<256, 8><<<g12, 256, SM256>>>(h, w0, yz, 512);
    k_gather<<<gatherB, 256>>>(b1, N);

    // layer 2
    k_mma<256, 8><<<g12, 256, SM256>>>(h, w1, yz, 512);
    k_gather<<<gatherB, 256>>>(b2, N);

    // layer 3
    k_mma<128, 4><<<g3, 256, SM128>>>(h, w3, yz, 128);
    k_gather3<<<gather3B, 256>>>(b3, out, N);
}

// round 8
// speedup vs baseline: 5.9453x; 1.0343x over previous
#include <cuda_runtime.h>
#include <cuda_fp16.h>
#include <cstdint>

#define NN   100000
#define MPAD 100096            // 782 * 128
#define FEAT 256
#define NT   782
#define SPAD 72
#define EMAX 800000
#define NB   391               // ceil(NN/256)

// ---------------- device scratch ----------------
__device__ int   g_degi[NN];           // zero-init; k_off restores zeros
__device__ int   g_ctr;                // reset in k_degi
__device__ float g_inv[NN];
__device__ int   g_off[NN];
__device__ int   g_end[NN];
__device__ int   g_cursor[NN];
__device__ int   g_srcl[EMAX];
__device__ __align__(16) __half g_yz[(size_t)MPAD * 512];
__device__ __align__(16) __half g_h[(size_t)MPAD * FEAT];
__device__ __align__(16) __half g_w[2][512 * 256];
__device__ __align__(16) __half g_w3[128 * 256];

// ---------------- helpers ----------------
__device__ __forceinline__ uint32_t smem_u32(const void* p) {
    uint32_t a;
    asm("{ .reg .u64 t; cvta.to.shared.u64 t, %1; cvt.u32.u64 %0, t; }" : "=r"(a) : "l"(p));
    return a;
}
__device__ __forceinline__ void cpa16(uint32_t dst, const void* src) {
    asm volatile("cp.async.cg.shared.global [%0], [%1], 16;" :: "r"(dst), "l"(src));
}

// ---------------- CSR build ----------------
__global__ void k_degi(const int* __restrict__ dst, int E) {
    if (blockIdx.x == 0 && threadIdx.x == 0) g_ctr = 0;
    int e = blockIdx.x * blockDim.x + threadIdx.x;
    if (e < E) atomicAdd(&g_degi[dst[e]], 1);
}
// single-pass: block scan + atomic range reservation (bucket order != node order, ok)
__global__ void k_off() {
    __shared__ int s[256];
    __shared__ int base;
    int i = blockIdx.x * 256 + threadIdx.x;
    int deg = (i < NN) ? g_degi[i] : 0;
    s[threadIdx.x] = deg;
    __syncthreads();
    for (int st = 1; st < 256; st <<= 1) {
        int add = (threadIdx.x >= st) ? s[threadIdx.x - st] : 0;
        __syncthreads();
        s[threadIdx.x] += add;
        __syncthreads();
    }
    if (threadIdx.x == 255) base = atomicAdd(&g_ctr, s[255]);
    __syncthreads();
    if (i < NN) {
        int beg = base + s[threadIdx.x] - deg;
        g_off[i] = beg;
        g_end[i] = beg + deg;
        g_cursor[i] = beg;
        g_inv[i] = 1.0f / fmaxf((float)deg, 1.0f);
        g_degi[i] = 0;                    // restore for next replay
    }
}
__global__ void k_fill(const int* __restrict__ src, const int* __restrict__ dst, int E) {
    int e = blockIdx.x * blockDim.x + threadIdx.x;
    if (e < E) {
        int pos = atomicAdd(&g_cursor[dst[e]], 1);
        g_srcl[pos] = src[e];
    }
}

// ---------------- convert kernels ----------------
__global__ void k_cvt_w(const float* __restrict__ Ws, const float* __restrict__ Wn,
                        int Nw, __half* __restrict__ w) {
    int idx = blockIdx.x * blockDim.x + threadIdx.x;
    if (idx >= 2 * Nw * FEAT) return;
    int n = idx >> 8, k = idx & 255;
    float v = (n < Nw) ? Ws[(size_t)k * Nw + n] : Wn[(size_t)k * Nw + (n - Nw)];
    w[idx] = __float2half_rn(v);
}
__global__ void k_cvt_x(const float* __restrict__ x, int M) {
    size_t tid = (size_t)blockIdx.x * blockDim.x + threadIdx.x;
    if (tid >= (size_t)MPAD * 64) return;
    int row = (int)(tid >> 6);
    float4 v = make_float4(0.f, 0.f, 0.f, 0.f);
    if (row < M) v = reinterpret_cast<const float4*>(x)[tid];
    uint2 o;
    __half2 p0 = __float22half2_rn(make_float2(v.x, v.y));
    __half2 p1 = __float22half2_rn(make_float2(v.z, v.w));
    o.x = *reinterpret_cast<uint32_t*>(&p0);
    o.y = *reinterpret_cast<uint32_t*>(&p1);
    *reinterpret_cast<uint2*>(g_h + tid * 4) = o;
}

// ---------------- fused gather + combine ----------------
__device__ __forceinline__ void acc8(float* acc, uint4 raw) {
    const __half2* hp = reinterpret_cast<const __half2*>(&raw);
#pragma unroll
    for (int q = 0; q < 4; q++) {
        float2 f = __half22float2(hp[q]);
        acc[q * 2 + 0] += f.x;
        acc[q * 2 + 1] += f.y;
    }
}
// layers 1/2: one warp per node, lane owns 8 cols of 256.
__global__ void k_gather(const float* __restrict__ bias, int M) {
    int wid  = threadIdx.x >> 5;
    int lane = threadIdx.x & 31;
    int node = blockIdx.x * (blockDim.x >> 5) + wid;
    if (node >= M) return;
    int beg = g_off[node], end = g_end[node];
    const __half* z = g_yz + 256 + lane * 8;   // z-half of yz rows
    float acc[8] = {0.f, 0.f, 0.f, 0.f, 0.f, 0.f, 0.f, 0.f};
    int j = beg;
    for (; j + 4 <= end; j += 4) {
        int s0 = g_srcl[j], s1 = g_srcl[j + 1];
        int s2 = g_srcl[j + 2], s3 = g_srcl[j + 3];
        uint4 r0 = *reinterpret_cast<const uint4*>(z + (size_t)s0 * 512);
        uint4 r1 = *reinterpret_cast<const uint4*>(z + (size_t)s1 * 512);
        uint4 r2 = *reinterpret_cast<const uint4*>(z + (size_t)s2 * 512);
        uint4 r3 = *reinterpret_cast<const uint4*>(z + (size_t)s3 * 512);
        acc8(acc, r0); acc8(acc, r1); acc8(acc, r2); acc8(acc, r3);
    }
    for (; j < end; j++) {
        int s0 = g_srcl[j];
        uint4 r0 = *reinterpret_cast<const uint4*>(z + (size_t)s0 * 512);
        acc8(acc, r0);
    }
    float inv = g_inv[node];
    uint4 rs = *reinterpret_cast<const uint4*>(g_yz + (size_t)node * 512 + lane * 8);
    const __half2* sp = reinterpret_cast<const __half2*>(&rs);
    float4 bva = *reinterpret_cast<const float4*>(bias + lane * 8);
    float4 bvb = *reinterpret_cast<const float4*>(bias + lane * 8 + 4);
    float bv[8] = {bva.x, bva.y, bva.z, bva.w, bvb.x, bvb.y, bvb.z, bvb.w};
    float v[8];
#pragma unroll
    for (int q = 0; q < 4; q++) {
        float2 ys = __half22float2(sp[q]);
        v[q * 2 + 0] = fmaxf(ys.x + inv * acc[q * 2 + 0] + bv[q * 2 + 0], 0.f);
        v[q * 2 + 1] = fmaxf(ys.y + inv * acc[q * 2 + 1] + bv[q * 2 + 1], 0.f);
    }
    uint4 o;
    __half2 p0 = __float22half2_rn(make_float2(v[0], v[1]));
    __half2 p1 = __float22half2_rn(make_float2(v[2], v[3]));
    __half2 p2 = __float22half2_rn(make_float2(v[4], v[5]));
    __half2 p3 = __float22half2_rn(make_float2(v[6], v[7]));
    o.x = *reinterpret_cast<uint32_t*>(&p0);
    o.y = *reinterpret_cast<uint32_t*>(&p1);
    o.z = *reinterpret_cast<uint32_t*>(&p2);
    o.w = *reinterpret_cast<uint32_t*>(&p3);
    *reinterpret_cast<uint4*>(g_h + (size_t)node * 256 + lane * 8) = o;
}
// layer 3: 8 lanes per node (4 nodes/warp), lane owns 8 of 64 cols, fp32 out.
__global__ void k_gather3(const float* __restrict__ bias, float* __restrict__ out, int M) {
    int wid  = threadIdx.x >> 5;
    int lane = threadIdx.x & 31;
    int node = (blockIdx.x * (blockDim.x >> 5) + wid) * 4 + (lane >> 3);
    int sub  = lane & 7;
    if (node >= M) return;
    int beg = g_off[node], end = g_end[node];
    const __half* z = g_yz + 64 + sub * 8;
    float acc[8] = {0.f, 0.f, 0.f, 0.f, 0.f, 0.f, 0.f, 0.f};
    int j = beg;
    for (; j + 4 <= end; j += 4) {
        int s0 = g_srcl[j], s1 = g_srcl[j + 1];
        int s2 = g_srcl[j + 2], s3 = g_srcl[j + 3];
        uint4 r0 = *reinterpret_cast<const uint4*>(z + (size_t)s0 * 128);
        uint4 r1 = *reinterpret_cast<const uint4*>(z + (size_t)s1 * 128);
        uint4 r2 = *reinterpret_cast<const uint4*>(z + (size_t)s2 * 128);
        uint4 r3 = *reinterpret_cast<const uint4*>(z + (size_t)s3 * 128);
        acc8(acc, r0); acc8(acc, r1); acc8(acc, r2); acc8(acc, r3);
    }
    for (; j < end; j++) {
        int s0 = g_srcl[j];
        uint4 r0 = *reinterpret_cast<const uint4*>(z + (size_t)s0 * 128);
        acc8(acc, r0);
    }
    float inv = g_inv[node];
    uint4 rs = *reinterpret_cast<const uint4*>(g_yz + (size_t)node * 128 + sub * 8);
    const __half2* sp = reinterpret_cast<const __half2*>(&rs);
    float4 bva = *reinterpret_cast<const float4*>(bias + sub * 8);
    float4 bvb = *reinterpret_cast<const float4*>(bias + sub * 8 + 4);
    float bv[8] = {bva.x, bva.y, bva.z, bva.w, bvb.x, bvb.y, bvb.z, bvb.w};
    float v[8];
#pragma unroll
    for (int q = 0; q < 4; q++) {
        float2 ys = __half22float2(sp[q]);
        v[q * 2 + 0] = ys.x + inv * acc[q * 2 + 0] + bv[q * 2 + 0];
        v[q * 2 + 1] = ys.y + inv * acc[q * 2 + 1] + bv[q * 2 + 1];
    }
    float* op = out + (size_t)node * 64 + sub * 8;
    *reinterpret_cast<float4*>(op)     = make_float4(v[0], v[1], v[2], v[3]);
    *reinterpret_cast<float4*>(op + 4) = make_float4(v[4], v[5], v[6], v[7]);
}

// ---------------- fp16 HMMA GEMM, 4-stage all-resident (K=256 = 4 chunks) ----------------
template<int BN, int NF>
__global__ __launch_bounds__(256) void k_mma(
    const __half* __restrict__ A, const __half* __restrict__ B,
    __half* __restrict__ Y, int NOUT)
{
    extern __shared__ __half dyn[];
    constexpr int AS  = 128 * SPAD;
    constexpr int BS  = BN * SPAD;
    constexpr int STG = AS + BS;

    const int t    = threadIdx.x;
    const int wid  = t >> 5;
    const int lane = t & 31;
    const int wm0  = (wid >> 2) << 6;
    const int wn0  = (wid & 3) * (BN / 4);
    const int row0 = blockIdx.y * 128;
    const int col0 = blockIdx.x * BN;

    const int lr = t >> 3;
    const int lc = (t & 7) << 3;

    float acc[4][NF][4];
#pragma unroll
    for (int mi = 0; mi < 4; mi++)
#pragma unroll
        for (int ni = 0; ni < NF; ni++)
#pragma unroll
            for (int r = 0; r < 4; r++) acc[mi][ni][r] = 0.0f;

    // issue ALL 4 chunk loads up front (no buffer reuse, max overlap)
#pragma unroll
    for (int kc = 0; kc < 4; kc++) {
        __half* dA = dyn + kc * STG;
        __half* dB = dA + AS;
        const __half* ap = A + (size_t)row0 * FEAT + kc * 64;
        const __half* bp = B + (size_t)col0 * FEAT + kc * 64;
#pragma unroll
        for (int j = 0; j < 4; j++) {
            int row = lr + j * 32;
            cpa16(smem_u32(dA + row * SPAD + lc), ap + (size_t)row * FEAT + lc);
        }
#pragma unroll
        for (int j = 0; j < BN / 32; j++) {
            int row = lr + j * 32;
            cpa16(smem_u32(dB + row * SPAD + lc), bp + (size_t)row * FEAT + lc);
        }
        asm volatile("cp.async.commit_group;" ::: "memory");
    }

#pragma unroll
    for (int kc = 0; kc < 4; kc++) {
        if (kc == 0)      asm volatile("cp.async.wait_group 3;" ::: "memory");
        else if (kc == 1) asm volatile("cp.async.wait_group 2;" ::: "memory");
        else if (kc == 2) asm volatile("cp.async.wait_group 1;" ::: "memory");
        else              asm volatile("cp.async.wait_group 0;" ::: "memory");
        __syncthreads();

        __half* dA = dyn + kc * STG;
        __half* dB = dA + AS;

#pragma unroll
        for (int ks = 0; ks < 4; ks++) {
            const int k0 = ks << 4;
            const int arow = wm0 + (lane & 15);
            const int acol = k0 + ((lane >> 4) << 3);
            const int brow = wn0 + (lane & 7) + ((lane >> 4) << 3);
            const int bcol = k0 + (((lane >> 3) & 1) << 3);

            uint32_t a[4][4], b[NF * 2];
#pragma unroll
            for (int mi = 0; mi < 4; mi++) {
                uint32_t ad = smem_u32(dA + (arow + mi * 16) * SPAD + acol);
                asm volatile("ldmatrix.sync.aligned.m8n8.x4.shared.b16 {%0,%1,%2,%3}, [%4];"
                             : "=r"(a[mi][0]), "=r"(a[mi][1]), "=r"(a[mi][2]), "=r"(a[mi][3])
                             : "r"(ad));
            }
#pragma unroll
            for (int nb = 0; nb < NF / 2; nb++) {
                uint32_t ad = smem_u32(dB + (brow + nb * 16) * SPAD + bcol);
                asm volatile("ldmatrix.sync.aligned.m8n8.x4.shared.b16 {%0,%1,%2,%3}, [%4];"
                             : "=r"(b[nb * 4 + 0]), "=r"(b[nb * 4 + 1]),
                               "=r"(b[nb * 4 + 2]), "=r"(b[nb * 4 + 3])
                             : "r"(ad));
            }
#pragma unroll
            for (int mi = 0; mi < 4; mi++)
#pragma unroll
                for (int ni = 0; ni < NF; ni++)
                    asm volatile(
                        "mma.sync.aligned.m16n8k16.row.col.f32.f16.f16.f32 "
                        "{%0,%1,%2,%3}, {%4,%5,%6,%7}, {%8,%9}, {%0,%1,%2,%3};"
                        : "+f"(acc[mi][ni][0]), "+f"(acc[mi][ni][1]),
                          "+f"(acc[mi][ni][2]), "+f"(acc[mi][ni][3])
                        : "r"(a[mi][0]), "r"(a[mi][1]), "r"(a[mi][2]), "r"(a[mi][3]),
                          "r"(b[ni * 2]), "r"(b[ni * 2 + 1]));
        }
    }

    const int crow = lane >> 2;
    const int ccol = (lane & 3) << 1;
#pragma unroll
    for (int mi = 0; mi < 4; mi++)
#pragma unroll
        for (int ni = 0; ni < NF; ni++) {
            int col = col0 + wn0 + ni * 8 + ccol;
#pragma unroll
            for (int h = 0; h < 2; h++) {
                int row = row0 + wm0 + mi * 16 + crow + h * 8;
                __half2 p = __float22half2_rn(
                    make_float2(acc[mi][ni][h * 2 + 0], acc[mi][ni][h * 2 + 1]));
                *reinterpret_cast<uint32_t*>(Y + (size_t)row * NOUT + col) =
                    *reinterpret_cast<uint32_t*>(&p);
            }
        }
}

// ---------------- launch ----------------
extern "C" void kernel_launch(void* const* d_in, const int* in_sizes, int n_in,
                              void* d_out, int out_size) {
    const float* x   = (const float*)d_in[0];
    const int*   src = (const int*)d_in[1];
    const int*   dst = (const int*)d_in[2];
    const float* Ws1 = (const float*)d_in[3];
    const float* Wn1 = (const float*)d_in[4];
    const float* b1  = (const float*)d_in[5];
    const float* Ws2 = (const float*)d_in[6];
    const float* Wn2 = (const float*)d_in[7];
    const float* b2  = (const float*)d_in[8];
    const float* Ws3 = (const float*)d_in[9];
    const float* Wn3 = (const float*)d_in[10];
    const float* b3  = (const float*)d_in[11];
    float* out = (float*)d_out;

    const int N = in_sizes[0] / FEAT;   // 100000
    const int E = in_sizes[1];          // 800000

    __half *yz, *h, *w0, *w1, *w3;
    cudaGetSymbolAddress((void**)&yz, g_yz);
    cudaGetSymbolAddress((void**)&h,  g_h);
    cudaGetSymbolAddress((void**)&w0, g_w);
    cudaGetSymbolAddress((void**)&w3, g_w3);
    w1 = w0 + (size_t)512 * 256;

    constexpr int SM256 = (128 * SPAD + 256 * SPAD) * 4 * 2;  // 221184 B
    constexpr int SM128 = (128 * SPAD + 128 * SPAD) * 4 * 2;  // 147456 B
    cudaFuncSetAttribute(k_mma<256, 8>, cudaFuncAttributeMaxDynamicSharedMemorySize, SM256);
    cudaFuncSetAttribute(k_mma<128, 4>, cudaFuncAttributeMaxDynamicSharedMemorySize, SM128);

    const int ZT = 256;
    const int cvtBlocks = (int)(((size_t)MPAD * 64 + ZT - 1) / ZT);

    // weights -> fp16 concat
    k_cvt_w<<<(2 * 256 * FEAT + ZT - 1) / ZT, ZT>>>(Ws1, Wn1, 256, w0);
    k_cvt_w<<<(2 * 256 * FEAT + ZT - 1) / ZT, ZT>>>(Ws2, Wn2, 256, w1);
    k_cvt_w<<<(2 * 64 * FEAT + ZT - 1) / ZT, ZT>>>(Ws3, Wn3, 64, w3);

    // CSR build (degi/ctr self-restore)
    k_degi<<<(E + ZT - 1) / ZT, ZT>>>(dst, E);
    k_off<<<NB, 256>>>();
    k_fill<<<(E + ZT - 1) / ZT, ZT>>>(src, dst, E);

    // x -> fp16
    k_cvt_x<<<cvtBlocks, ZT>>>(x, N);

    dim3 g12(2, NT);
    dim3 g3(1, NT);
    const int gatherB = (N + 7) / 8;
    const int gather3B = (N + 31) / 32;

    // layer 1
    k_mma<256, 8><<<g12, 256, SM256>>>(h, w0, yz, 512);
    k_gather<<<gatherB, 256>>>(b1, N);

    // layer 2
    k_mma<256, 8><<<g12, 256, SM256>>>(h, w1, yz, 512);
    k_gather<<<gatherB, 256>>>(b2, N);

    // layer 3
    k_mma<128, 4><<<g3, 256, SM128>>>(h, w3, yz, 128);
    k_gather3<<<gather3B, 256>>>(b3, out, N);
}